// round 5
// baseline (speedup 1.0000x reference)
#include <cuda_runtime.h>

// Problem constants
#define B_ 4
#define S_ 2048
#define E_ 1024
#define H_ 16
#define D_ 64

// ---------------- scratch ----------------
__device__ float g_Q[B_*H_*S_*D_];     // [B,H,S,D]
__device__ float g_K[B_*H_*S_*D_];
__device__ float g_V[B_*H_*S_*D_];
__device__ float g_pooled[B_*E_];      // column sums of attention output (pre mean-scale)
__device__ float g_o[B_*E_];           // out_proj output
__device__ float g_nrm[B_];            // squared norms
__device__ float g_score[B_];          // pre-tanh score

// ---------------- helpers ----------------
__device__ __forceinline__ unsigned f2tf(float x) {
    unsigned r; asm("cvt.rna.tf32.f32 %0, %1;" : "=r"(r) : "f"(x)); return r;
}
__device__ __forceinline__ float f2tff(float x) { return __uint_as_float(f2tf(x)); }

// D += A(m16k8,row) * B(k8n8,col), tf32
__device__ __forceinline__ void mma8(float* c, const unsigned* a, const unsigned* b) {
    asm("mma.sync.aligned.m16n8k8.row.col.f32.tf32.tf32.f32 "
        "{%0,%1,%2,%3}, {%4,%5,%6,%7}, {%8,%9}, {%0,%1,%2,%3};"
        : "+f"(c[0]), "+f"(c[1]), "+f"(c[2]), "+f"(c[3])
        : "r"(a[0]), "r"(a[1]), "r"(a[2]), "r"(a[3]), "r"(b[0]), "r"(b[1]));
}

// fast exp on the FMA/ALU pipes (input must already be clamped to [-80, 60])
__device__ __forceinline__ float exp_fast(float s) {
    float y = s * 1.4426950408889634f;
    float t = y + 12582912.f;             // round-to-nearest int via magic number
    float n = t - 12582912.f;
    float f = y - n;                      // f in [-0.5, 0.5]
    float p = fmaf(fmaf(fmaf(fmaf(0.009618130f, f,
                    0.05550411f), f, 0.2401597f), f, 0.6931472f), f, 1.0f);
    return __int_as_float(__float_as_int(p) + (__float_as_int(t) << 23));
}
// truncate fp32 to tf32 bit pattern (keeps P consistent between lsum and PV mma)
__device__ __forceinline__ float tf_trunc(float x) {
    return __uint_as_float(__float_as_uint(x) & 0xffffe000u);
}

// =====================================================================
// zero scratch accumulators
// =====================================================================
__global__ void zero_kernel() {
    int i = blockIdx.x * blockDim.x + threadIdx.x;
    if (i < B_*E_) g_pooled[i] = 0.f;
    if (i < B_) { g_nrm[i] = 0.f; g_score[i] = 0.f; }
}

// =====================================================================
// QKV projection via tf32 mma: Y = x @ W^T + b, scatter to [B,H,S,D]
// M=8192 N=1024 K=1024. BM=128 BN=128 BK=32, 256 threads (8 warps, 2x4),
// warp tile 64x32 (mt=4, nt=4).
// =====================================================================
__global__ __launch_bounds__(256) void qkv_mma(
    const float* __restrict__ x,
    const float* __restrict__ Wq, const float* __restrict__ bq,
    const float* __restrict__ Wk, const float* __restrict__ bk,
    const float* __restrict__ Wv, const float* __restrict__ bv)
{
    __shared__ __align__(16) float As[128][36];   // [m][k], pad->bank 4r+c conflict-free
    __shared__ __align__(16) float Bs[128][36];   // [n][k]

    const int z = blockIdx.z;
    const float* __restrict__ W    = (z == 0) ? Wq : ((z == 1) ? Wk : Wv);
    const float* __restrict__ bias = (z == 0) ? bq : ((z == 1) ? bk : bv);
    float* __restrict__ out        = (z == 0) ? g_Q : ((z == 1) ? g_K : g_V);

    const int tid  = threadIdx.x;
    const int lane = tid & 31, wid = tid >> 5;
    const int wm = wid >> 2, wn = wid & 3;
    const int m0 = blockIdx.y * 128, n0 = blockIdx.x * 128;
    const int r = lane >> 2, c = lane & 3;

    float acc[4][4][4];
    #pragma unroll
    for (int mt = 0; mt < 4; mt++)
        #pragma unroll
        for (int nt = 0; nt < 4; nt++)
            #pragma unroll
            for (int j = 0; j < 4; j++) acc[mt][nt][j] = 0.f;

    const int lr  = tid >> 3;         // 0..31
    const int lc4 = (tid & 7) * 4;    // 0..28

    for (int k0 = 0; k0 < E_; k0 += 32) {
        __syncthreads();
        #pragma unroll
        for (int it = 0; it < 4; it++) {
            int rr = lr + it * 32;
            float4 va = *(const float4*)(x + (size_t)(m0 + rr) * E_ + k0 + lc4);
            float4 vb = *(const float4*)(W + (size_t)(n0 + rr) * E_ + k0 + lc4);
            float4 sa, sb;
            sa.x = f2tff(va.x); sa.y = f2tff(va.y); sa.z = f2tff(va.z); sa.w = f2tff(va.w);
            sb.x = f2tff(vb.x); sb.y = f2tff(vb.y); sb.z = f2tff(vb.z); sb.w = f2tff(vb.w);
            *(float4*)&As[rr][lc4] = sa;
            *(float4*)&Bs[rr][lc4] = sb;
        }
        __syncthreads();

        #pragma unroll
        for (int ks = 0; ks < 4; ks++) {
            unsigned a[4][4];
            #pragma unroll
            for (int mt = 0; mt < 4; mt++) {
                int row = wm * 64 + mt * 16;
                a[mt][0] = __float_as_uint(As[row + r    ][ks*8 + c    ]);
                a[mt][1] = __float_as_uint(As[row + r + 8][ks*8 + c    ]);
                a[mt][2] = __float_as_uint(As[row + r    ][ks*8 + c + 4]);
                a[mt][3] = __float_as_uint(As[row + r + 8][ks*8 + c + 4]);
            }
            #pragma unroll
            for (int nt = 0; nt < 4; nt++) {
                int col = wn * 32 + nt * 8;
                unsigned bf[2];
                bf[0] = __float_as_uint(Bs[col + r][ks*8 + c    ]);
                bf[1] = __float_as_uint(Bs[col + r][ks*8 + c + 4]);
                #pragma unroll
                for (int mt = 0; mt < 4; mt++) mma8(acc[mt][nt], a[mt], bf);
            }
        }
    }

    // epilogue: bias + scatter to [B,H,S,D]
    #pragma unroll
    for (int nt = 0; nt < 4; nt++) {
        int coln = n0 + wn * 32 + nt * 8 + 2 * c;
        int h = coln >> 6, d = coln & 63;
        float bv0 = bias[coln], bv1 = bias[coln + 1];
        #pragma unroll
        for (int mt = 0; mt < 4; mt++) {
            int gm = m0 + wm * 64 + mt * 16 + r;
            int bb = gm >> 11, s = gm & (S_ - 1);
            float2 v0 = make_float2(acc[mt][nt][0] + bv0, acc[mt][nt][1] + bv1);
            float2 v1 = make_float2(acc[mt][nt][2] + bv0, acc[mt][nt][3] + bv1);
            *(float2*)(out + (size_t)((bb*H_ + h)*S_ + s    ) * D_ + d) = v0;
            *(float2*)(out + (size_t)((bb*H_ + h)*S_ + s + 8) * D_ + d) = v1;
        }
    }
}

// =====================================================================
// Flash attention via tf32 mma, no-max softmax with polynomial exp.
// Block: 256 query rows (8 warps x 32 rows, mt=2), key tile 64.
// Fuses the mean-over-S via atomicAdd into g_pooled.
// =====================================================================
#define AT_ST 68    // padded row stride -> banks 4r+c, conflict-free frag loads
#define ATTN_SMEM ((256 + 64 + 64 + 256) * AT_ST * 4 + 64 * 4)

__global__ __launch_bounds__(256) void attn_mma(const int* __restrict__ mask)
{
    extern __shared__ __align__(16) float sm[];
    float* Qs = sm;                        // [256][AT_ST] tf32, pre-scaled
    float* Ks = Qs + 256 * AT_ST;          // [64][AT_ST]  tf32
    float* Vs = Ks + 64 * AT_ST;           // [64][AT_ST]  tf32
    float* Ps = Vs + 64 * AT_ST;           // [256][AT_ST] tf32 (truncated exp)
    float* smf = Ps + 256 * AT_ST;         // [64] mask add (-1e9 / 0)

    const int tid  = threadIdx.x;
    const int lane = tid & 31, wid = tid >> 5;
    const int bh = blockIdx.y, b = bh >> 4;
    const int m0 = blockIdx.x * 256;
    const int r = lane >> 2, c = lane & 3;
    const int wrow = wid * 32;

    const float* Qg = g_Q + (size_t)(bh * S_ + m0) * D_;
    const float* Kg = g_K + (size_t)bh * S_ * D_;
    const float* Vg = g_V + (size_t)bh * S_ * D_;

    // Q tile (fold 1/sqrt(D), convert tf32)
    #pragma unroll
    for (int it = 0; it < 16; it++) {
        int lin = tid + it * 256;
        int rr = lin >> 4, c4 = (lin & 15) * 4;
        float4 v = *(const float4*)(Qg + (size_t)rr * D_ + c4);
        float4 sv;
        sv.x = f2tff(v.x * 0.125f); sv.y = f2tff(v.y * 0.125f);
        sv.z = f2tff(v.z * 0.125f); sv.w = f2tff(v.w * 0.125f);
        *(float4*)&Qs[rr * AT_ST + c4] = sv;
    }

    float oac[2][8][4];
    #pragma unroll
    for (int mt = 0; mt < 2; mt++)
        #pragma unroll
        for (int dt = 0; dt < 8; dt++)
            #pragma unroll
            for (int j = 0; j < 4; j++) oac[mt][dt][j] = 0.f;
    float lsum[2][2] = {{0.f, 0.f}, {0.f, 0.f}};

    for (int n0 = 0; n0 < S_; n0 += 64) {
        __syncthreads();
        #pragma unroll
        for (int it = 0; it < 4; it++) {
            int lin = tid + it * 256;
            int rr = lin >> 4, c4 = (lin & 15) * 4;
            float4 kv = *(const float4*)(Kg + (size_t)(n0 + rr) * D_ + c4);
            float4 vv = *(const float4*)(Vg + (size_t)(n0 + rr) * D_ + c4);
            float4 sk, sv;
            sk.x = f2tff(kv.x); sk.y = f2tff(kv.y); sk.z = f2tff(kv.z); sk.w = f2tff(kv.w);
            sv.x = f2tff(vv.x); sv.y = f2tff(vv.y); sv.z = f2tff(vv.z); sv.w = f2tff(vv.w);
            *(float4*)&Ks[rr * AT_ST + c4] = sk;
            *(float4*)&Vs[rr * AT_ST + c4] = sv;
        }
        if (tid < 64) smf[tid] = mask[b * S_ + n0 + tid] ? 0.f : -1e9f;
        __syncthreads();

        // ---- S = Q K^T ----
        float sc[2][8][4];
        #pragma unroll
        for (int mt = 0; mt < 2; mt++)
            #pragma unroll
            for (int nt = 0; nt < 8; nt++)
                #pragma unroll
                for (int j = 0; j < 4; j++) sc[mt][nt][j] = 0.f;

        #pragma unroll
        for (int ks = 0; ks < 8; ks++) {
            unsigned a[2][4];
            #pragma unroll
            for (int mt = 0; mt < 2; mt++) {
                int row = wrow + mt * 16;
                a[mt][0] = __float_as_uint(Qs[(row + r    ) * AT_ST + ks*8 + c    ]);
                a[mt][1] = __float_as_uint(Qs[(row + r + 8) * AT_ST + ks*8 + c    ]);
                a[mt][2] = __float_as_uint(Qs[(row + r    ) * AT_ST + ks*8 + c + 4]);
                a[mt][3] = __float_as_uint(Qs[(row + r + 8) * AT_ST + ks*8 + c + 4]);
            }
            #pragma unroll
            for (int nt = 0; nt < 8; nt++) {
                unsigned bf[2];
                bf[0] = __float_as_uint(Ks[(nt*8 + r) * AT_ST + ks*8 + c    ]);
                bf[1] = __float_as_uint(Ks[(nt*8 + r) * AT_ST + ks*8 + c + 4]);
                mma8(sc[0][nt], a[0], bf);
                mma8(sc[1][nt], a[1], bf);
            }
        }

        // ---- exp (poly, FMA pipe), accumulate row sums, truncate to tf32 ----
        #pragma unroll
        for (int nt = 0; nt < 8; nt++) {
            float mf0 = smf[nt*8 + 2*c];
            float mf1 = smf[nt*8 + 2*c + 1];
            #pragma unroll
            for (int mt = 0; mt < 2; mt++) {
                float e0 = tf_trunc(exp_fast(fminf(fmaxf(sc[mt][nt][0] + mf0, -80.f), 60.f)));
                float e1 = tf_trunc(exp_fast(fminf(fmaxf(sc[mt][nt][1] + mf1, -80.f), 60.f)));
                float e2 = tf_trunc(exp_fast(fminf(fmaxf(sc[mt][nt][2] + mf0, -80.f), 60.f)));
                float e3 = tf_trunc(exp_fast(fminf(fmaxf(sc[mt][nt][3] + mf1, -80.f), 60.f)));
                lsum[mt][0] += e0 + e1;
                lsum[mt][1] += e2 + e3;
                sc[mt][nt][0] = e0; sc[mt][nt][1] = e1;
                sc[mt][nt][2] = e2; sc[mt][nt][3] = e3;
            }
        }

        // ---- P to smem (warp-private rows) ----
        #pragma unroll
        for (int mt = 0; mt < 2; mt++) {
            int row = wrow + mt * 16;
            #pragma unroll
            for (int nt = 0; nt < 8; nt++) {
                *(float2*)&Ps[(row + r    ) * AT_ST + nt*8 + 2*c] =
                    make_float2(sc[mt][nt][0], sc[mt][nt][1]);
                *(float2*)&Ps[(row + r + 8) * AT_ST + nt*8 + 2*c] =
                    make_float2(sc[mt][nt][2], sc[mt][nt][3]);
            }
        }
        __syncwarp();

        // ---- O += P V ----
        #pragma unroll
        for (int ks = 0; ks < 8; ks++) {
            unsigned a[2][4];
            #pragma unroll
            for (int mt = 0; mt < 2; mt++) {
                int row = wrow + mt * 16;
                a[mt][0] = __float_as_uint(Ps[(row + r    ) * AT_ST + ks*8 + c    ]);
                a[mt][1] = __float_as_uint(Ps[(row + r + 8) * AT_ST + ks*8 + c    ]);
                a[mt][2] = __float_as_uint(Ps[(row + r    ) * AT_ST + ks*8 + c + 4]);
                a[mt][3] = __float_as_uint(Ps[(row + r + 8) * AT_ST + ks*8 + c + 4]);
            }
            #pragma unroll
            for (int dt = 0; dt < 8; dt++) {
                unsigned bf[2];
                bf[0] = __float_as_uint(Vs[(ks*8 + c    ) * AT_ST + dt*8 + r]);
                bf[1] = __float_as_uint(Vs[(ks*8 + c + 4) * AT_ST + dt*8 + r]);
                mma8(oac[0][dt], a[0], bf);
                mma8(oac[1][dt], a[1], bf);
            }
        }
    }

    // ---- epilogue: normalize rows, fused mean via atomics ----
    #pragma unroll
    for (int mt = 0; mt < 2; mt++)
        #pragma unroll
        for (int j = 0; j < 2; j++) {
            float v = lsum[mt][j];
            v += __shfl_xor_sync(0xffffffffu, v, 1);
            v += __shfl_xor_sync(0xffffffffu, v, 2);
            lsum[mt][j] = 1.f / v;
        }

    const int h = bh & 15;
    #pragma unroll
    for (int dt = 0; dt < 8; dt++) {
        float p0 = oac[0][dt][0]*lsum[0][0] + oac[0][dt][2]*lsum[0][1]
                 + oac[1][dt][0]*lsum[1][0] + oac[1][dt][2]*lsum[1][1];
        float p1 = oac[0][dt][1]*lsum[0][0] + oac[0][dt][3]*lsum[0][1]
                 + oac[1][dt][1]*lsum[1][0] + oac[1][dt][3]*lsum[1][1];
        p0 += __shfl_xor_sync(0xffffffffu, p0, 4);
        p0 += __shfl_xor_sync(0xffffffffu, p0, 8);
        p0 += __shfl_xor_sync(0xffffffffu, p0, 16);
        p1 += __shfl_xor_sync(0xffffffffu, p1, 4);
        p1 += __shfl_xor_sync(0xffffffffu, p1, 8);
        p1 += __shfl_xor_sync(0xffffffffu, p1, 16);
        if (lane < 4) {
            atomicAdd(&g_pooled[b*E_ + h*64 + dt*8 + 2*c    ], p0);
            atomicAdd(&g_pooled[b*E_ + h*64 + dt*8 + 2*c + 1], p1);
        }
    }
}

// =====================================================================
// head A: o = (pooled/S) @ Wo^T + bo ; accumulate squared norm
// grid (128, B), 256 thr; warp per output column
// =====================================================================
__global__ __launch_bounds__(256) void headA_kernel(
    const float* __restrict__ Wo, const float* __restrict__ bo)
{
    const int b = blockIdx.y;
    const int n = blockIdx.x * 8 + (threadIdx.x >> 5);
    const int lane = threadIdx.x & 31;
    const float* pr = g_pooled + b * E_;
    const float* wr = Wo + (size_t)n * E_;
    float acc = 0.f;
    #pragma unroll
    for (int i = 0; i < 8; i++) {
        int k = i * 128 + lane * 4;
        float4 w = *(const float4*)(wr + k);
        float4 p = *(const float4*)(pr + k);
        acc += p.x*w.x + p.y*w.y + p.z*w.z + p.w*w.w;
    }
    #pragma unroll
    for (int off = 16; off > 0; off >>= 1)
        acc += __shfl_xor_sync(0xffffffffu, acc, off);
    if (lane == 0) {
        float o = acc * (1.0f / S_) + bo[n];
        g_o[b * E_ + n] = o;
        atomicAdd(&g_nrm[b], o * o);
    }
}

// =====================================================================
// head B: u = o/||o|| - text ; h = relu(u @ W1^T + b1) ; score += h*W2
// grid (64, B), 256 thr; warp per hidden row
// =====================================================================
__global__ __launch_bounds__(256) void headB_kernel(
    const float* __restrict__ text,
    const float* __restrict__ W1, const float* __restrict__ b1,
    const float* __restrict__ W2)
{
    const int b = blockIdx.y;
    const int rr = blockIdx.x * 8 + (threadIdx.x >> 5);
    const int lane = threadIdx.x & 31;
    const float rinv = rsqrtf(g_nrm[b]);
    const float* orow = g_o + b * E_;
    const float* trow = text + b * E_;
    const float* wr = W1 + (size_t)rr * E_;
    float acc = 0.f;
    #pragma unroll
    for (int i = 0; i < 8; i++) {
        int k = i * 128 + lane * 4;
        float4 w = *(const float4*)(wr + k);
        float4 o = *(const float4*)(orow + k);
        float4 t = *(const float4*)(trow + k);
        acc += (o.x*rinv - t.x)*w.x + (o.y*rinv - t.y)*w.y
             + (o.z*rinv - t.z)*w.z + (o.w*rinv - t.w)*w.w;
    }
    #pragma unroll
    for (int off = 16; off > 0; off >>= 1)
        acc += __shfl_xor_sync(0xffffffffu, acc, off);
    if (lane == 0) {
        float hv = fmaxf(acc + b1[rr], 0.f);
        atomicAdd(&g_score[b], hv * W2[rr]);
    }
}

__global__ void headC_kernel(const float* __restrict__ b2, float* __restrict__ out)
{
    int i = threadIdx.x;
    if (i < B_) out[i] = tanhf(g_score[i] + b2[0]);
}

// =====================================================================
// Launch
// =====================================================================
extern "C" void kernel_launch(void* const* d_in, const int* in_sizes, int n_in,
                              void* d_out, int out_size)
{
    (void)in_sizes; (void)n_in; (void)out_size;
    const float* x    = (const float*)d_in[0];
    const int*   mask = (const int*)  d_in[1];
    const float* text = (const float*)d_in[2];
    const float* Wq = (const float*)d_in[3];
    const float* bq = (const float*)d_in[4];
    const float* Wk = (const float*)d_in[5];
    const float* bk = (const float*)d_in[6];
    const float* Wv = (const float*)d_in[7];
    const float* bv = (const float*)d_in[8];
    const float* Wo = (const float*)d_in[9];
    const float* bo = (const float*)d_in[10];
    const float* W1 = (const float*)d_in[11];
    const float* b1 = (const float*)d_in[12];
    const float* W2 = (const float*)d_in[13];
    const float* b2 = (const float*)d_in[14];
    float* out = (float*)d_out;

    cudaFuncSetAttribute(attn_mma, cudaFuncAttributeMaxDynamicSharedMemorySize, ATTN_SMEM);

    zero_kernel<<<16, 256>>>();
    qkv_mma<<<dim3(8, 64, 3), 256>>>(x, Wq, bq, Wk, bk, Wv, bv);
    attn_mma<<<dim3(8, 64), 256, ATTN_SMEM>>>(mask);
    headA_kernel<<<dim3(128, B_), 256>>>(Wo, bo);
    headB_kernel<<<dim3(64, B_), 256>>>(text, W1, b1, W2);
    headC_kernel<<<1, 32>>>(b2, out);
}

// round 6
// speedup vs baseline: 1.0033x; 1.0033x over previous
#include <cuda_runtime.h>

// Problem constants
#define B_ 4
#define S_ 2048
#define E_ 1024
#define H_ 16
#define D_ 64

// ---------------- scratch ----------------
__device__ float g_Q[B_*H_*S_*D_];     // [B,H,S,D]
__device__ float g_K[B_*H_*S_*D_];
__device__ float g_V[B_*H_*S_*D_];
__device__ float g_pooled[B_*E_];      // column sums of attention output (pre mean-scale)
__device__ float g_o[B_*E_];           // out_proj output
__device__ float g_nrm[B_];            // squared norms
__device__ float g_score[B_];          // pre-tanh score

// ---------------- helpers ----------------
__device__ __forceinline__ unsigned f2tf(float x) {
    unsigned r; asm("cvt.rna.tf32.f32 %0, %1;" : "=r"(r) : "f"(x)); return r;
}
__device__ __forceinline__ float f2tff(float x) { return __uint_as_float(f2tf(x)); }

// D += A(m16k8,row) * B(k8n8,col), tf32
__device__ __forceinline__ void mma8(float* c, const unsigned* a, const unsigned* b) {
    asm("mma.sync.aligned.m16n8k8.row.col.f32.tf32.tf32.f32 "
        "{%0,%1,%2,%3}, {%4,%5,%6,%7}, {%8,%9}, {%0,%1,%2,%3};"
        : "+f"(c[0]), "+f"(c[1]), "+f"(c[2]), "+f"(c[3])
        : "r"(a[0]), "r"(a[1]), "r"(a[2]), "r"(a[3]), "r"(b[0]), "r"(b[1]));
}

// fast exp on the FMA/ALU pipes (input must already be clamped to [-80, 60])
__device__ __forceinline__ float exp_fast(float s) {
    float y = s * 1.4426950408889634f;
    float t = y + 12582912.f;             // round-to-nearest int via magic number
    float n = t - 12582912.f;
    float f = y - n;                      // f in [-0.5, 0.5]
    float p = fmaf(fmaf(fmaf(fmaf(0.009618130f, f,
                    0.05550411f), f, 0.2401597f), f, 0.6931472f), f, 1.0f);
    return __int_as_float(__float_as_int(p) + (__float_as_int(t) << 23));
}
// truncate fp32 to tf32 bit pattern (keeps P consistent between lsum and PV mma)
__device__ __forceinline__ float tf_trunc(float x) {
    return __uint_as_float(__float_as_uint(x) & 0xffffe000u);
}

// =====================================================================
// zero scratch accumulators
// =====================================================================
__global__ void zero_kernel() {
    int i = blockIdx.x * blockDim.x + threadIdx.x;
    if (i < B_*E_) g_pooled[i] = 0.f;
    if (i < B_) { g_nrm[i] = 0.f; g_score[i] = 0.f; }
}

// =====================================================================
// QKV projection via tf32 mma: Y = x @ W^T + b, scatter to [B,H,S,D]
// M=8192 N=1024 K=1024. BM=128 BN=128 BK=32, 256 threads (8 warps, 2x4),
// warp tile 64x32 (mt=4, nt=4).
// =====================================================================
__global__ __launch_bounds__(256) void qkv_mma(
    const float* __restrict__ x,
    const float* __restrict__ Wq, const float* __restrict__ bq,
    const float* __restrict__ Wk, const float* __restrict__ bk,
    const float* __restrict__ Wv, const float* __restrict__ bv)
{
    __shared__ __align__(16) float As[128][36];   // [m][k], pad->bank 4r+c conflict-free
    __shared__ __align__(16) float Bs[128][36];   // [n][k]

    const int z = blockIdx.z;
    const float* __restrict__ W    = (z == 0) ? Wq : ((z == 1) ? Wk : Wv);
    const float* __restrict__ bias = (z == 0) ? bq : ((z == 1) ? bk : bv);
    float* __restrict__ out        = (z == 0) ? g_Q : ((z == 1) ? g_K : g_V);

    const int tid  = threadIdx.x;
    const int lane = tid & 31, wid = tid >> 5;
    const int wm = wid >> 2, wn = wid & 3;
    const int m0 = blockIdx.y * 128, n0 = blockIdx.x * 128;
    const int r = lane >> 2, c = lane & 3;

    float acc[4][4][4];
    #pragma unroll
    for (int mt = 0; mt < 4; mt++)
        #pragma unroll
        for (int nt = 0; nt < 4; nt++)
            #pragma unroll
            for (int j = 0; j < 4; j++) acc[mt][nt][j] = 0.f;

    const int lr  = tid >> 3;         // 0..31
    const int lc4 = (tid & 7) * 4;    // 0..28

    for (int k0 = 0; k0 < E_; k0 += 32) {
        __syncthreads();
        #pragma unroll
        for (int it = 0; it < 4; it++) {
            int rr = lr + it * 32;
            float4 va = *(const float4*)(x + (size_t)(m0 + rr) * E_ + k0 + lc4);
            float4 vb = *(const float4*)(W + (size_t)(n0 + rr) * E_ + k0 + lc4);
            float4 sa, sb;
            sa.x = f2tff(va.x); sa.y = f2tff(va.y); sa.z = f2tff(va.z); sa.w = f2tff(va.w);
            sb.x = f2tff(vb.x); sb.y = f2tff(vb.y); sb.z = f2tff(vb.z); sb.w = f2tff(vb.w);
            *(float4*)&As[rr][lc4] = sa;
            *(float4*)&Bs[rr][lc4] = sb;
        }
        __syncthreads();

        #pragma unroll
        for (int ks = 0; ks < 4; ks++) {
            unsigned a[4][4];
            #pragma unroll
            for (int mt = 0; mt < 4; mt++) {
                int row = wm * 64 + mt * 16;
                a[mt][0] = __float_as_uint(As[row + r    ][ks*8 + c    ]);
                a[mt][1] = __float_as_uint(As[row + r + 8][ks*8 + c    ]);
                a[mt][2] = __float_as_uint(As[row + r    ][ks*8 + c + 4]);
                a[mt][3] = __float_as_uint(As[row + r + 8][ks*8 + c + 4]);
            }
            #pragma unroll
            for (int nt = 0; nt < 4; nt++) {
                int col = wn * 32 + nt * 8;
                unsigned bf[2];
                bf[0] = __float_as_uint(Bs[col + r][ks*8 + c    ]);
                bf[1] = __float_as_uint(Bs[col + r][ks*8 + c + 4]);
                #pragma unroll
                for (int mt = 0; mt < 4; mt++) mma8(acc[mt][nt], a[mt], bf);
            }
        }
    }

    // epilogue: bias + scatter to [B,H,S,D]
    #pragma unroll
    for (int nt = 0; nt < 4; nt++) {
        int coln = n0 + wn * 32 + nt * 8 + 2 * c;
        int h = coln >> 6, d = coln & 63;
        float bv0 = bias[coln], bv1 = bias[coln + 1];
        #pragma unroll
        for (int mt = 0; mt < 4; mt++) {
            int gm = m0 + wm * 64 + mt * 16 + r;
            int bb = gm >> 11, s = gm & (S_ - 1);
            float2 v0 = make_float2(acc[mt][nt][0] + bv0, acc[mt][nt][1] + bv1);
            float2 v1 = make_float2(acc[mt][nt][2] + bv0, acc[mt][nt][3] + bv1);
            *(float2*)(out + (size_t)((bb*H_ + h)*S_ + s    ) * D_ + d) = v0;
            *(float2*)(out + (size_t)((bb*H_ + h)*S_ + s + 8) * D_ + d) = v1;
        }
    }
}

// =====================================================================
// Flash attention via tf32 mma, no-max softmax with polynomial exp.
// Block: 256 query rows (8 warps x 32 rows, mt=2), key tile 64.
// Fuses the mean-over-S via atomicAdd into g_pooled.
// =====================================================================
#define AT_ST 68    // padded row stride -> banks 4r+c, conflict-free frag loads
#define ATTN_SMEM ((256 + 64 + 64 + 256) * AT_ST * 4 + 64 * 4)

__global__ __launch_bounds__(256) void attn_mma(const int* __restrict__ mask)
{
    extern __shared__ __align__(16) float sm[];
    float* Qs = sm;                        // [256][AT_ST] tf32, pre-scaled
    float* Ks = Qs + 256 * AT_ST;          // [64][AT_ST]  tf32
    float* Vs = Ks + 64 * AT_ST;           // [64][AT_ST]  tf32
    float* Ps = Vs + 64 * AT_ST;           // [256][AT_ST] tf32 (truncated exp)
    float* smf = Ps + 256 * AT_ST;         // [64] mask add (-1e9 / 0)

    const int tid  = threadIdx.x;
    const int lane = tid & 31, wid = tid >> 5;
    const int bh = blockIdx.y, b = bh >> 4;
    const int m0 = blockIdx.x * 256;
    const int r = lane >> 2, c = lane & 3;
    const int wrow = wid * 32;

    const float* Qg = g_Q + (size_t)(bh * S_ + m0) * D_;
    const float* Kg = g_K + (size_t)bh * S_ * D_;
    const float* Vg = g_V + (size_t)bh * S_ * D_;

    // Q tile (fold 1/sqrt(D), convert tf32)
    #pragma unroll
    for (int it = 0; it < 16; it++) {
        int lin = tid + it * 256;
        int rr = lin >> 4, c4 = (lin & 15) * 4;
        float4 v = *(const float4*)(Qg + (size_t)rr * D_ + c4);
        float4 sv;
        sv.x = f2tff(v.x * 0.125f); sv.y = f2tff(v.y * 0.125f);
        sv.z = f2tff(v.z * 0.125f); sv.w = f2tff(v.w * 0.125f);
        *(float4*)&Qs[rr * AT_ST + c4] = sv;
    }

    float oac[2][8][4];
    #pragma unroll
    for (int mt = 0; mt < 2; mt++)
        #pragma unroll
        for (int dt = 0; dt < 8; dt++)
            #pragma unroll
            for (int j = 0; j < 4; j++) oac[mt][dt][j] = 0.f;
    float lsum[2][2] = {{0.f, 0.f}, {0.f, 0.f}};

    for (int n0 = 0; n0 < S_; n0 += 64) {
        __syncthreads();
        #pragma unroll
        for (int it = 0; it < 4; it++) {
            int lin = tid + it * 256;
            int rr = lin >> 4, c4 = (lin & 15) * 4;
            float4 kv = *(const float4*)(Kg + (size_t)(n0 + rr) * D_ + c4);
            float4 vv = *(const float4*)(Vg + (size_t)(n0 + rr) * D_ + c4);
            float4 sk, sv;
            sk.x = f2tff(kv.x); sk.y = f2tff(kv.y); sk.z = f2tff(kv.z); sk.w = f2tff(kv.w);
            sv.x = f2tff(vv.x); sv.y = f2tff(vv.y); sv.z = f2tff(vv.z); sv.w = f2tff(vv.w);
            *(float4*)&Ks[rr * AT_ST + c4] = sk;
            *(float4*)&Vs[rr * AT_ST + c4] = sv;
        }
        if (tid < 64) smf[tid] = mask[b * S_ + n0 + tid] ? 0.f : -1e9f;
        __syncthreads();

        // ---- S = Q K^T ----
        float sc[2][8][4];
        #pragma unroll
        for (int mt = 0; mt < 2; mt++)
            #pragma unroll
            for (int nt = 0; nt < 8; nt++)
                #pragma unroll
                for (int j = 0; j < 4; j++) sc[mt][nt][j] = 0.f;

        #pragma unroll
        for (int ks = 0; ks < 8; ks++) {
            unsigned a[2][4];
            #pragma unroll
            for (int mt = 0; mt < 2; mt++) {
                int row = wrow + mt * 16;
                a[mt][0] = __float_as_uint(Qs[(row + r    ) * AT_ST + ks*8 + c    ]);
                a[mt][1] = __float_as_uint(Qs[(row + r + 8) * AT_ST + ks*8 + c    ]);
                a[mt][2] = __float_as_uint(Qs[(row + r    ) * AT_ST + ks*8 + c + 4]);
                a[mt][3] = __float_as_uint(Qs[(row + r + 8) * AT_ST + ks*8 + c + 4]);
            }
            #pragma unroll
            for (int nt = 0; nt < 8; nt++) {
                unsigned bf[2];
                bf[0] = __float_as_uint(Ks[(nt*8 + r) * AT_ST + ks*8 + c    ]);
                bf[1] = __float_as_uint(Ks[(nt*8 + r) * AT_ST + ks*8 + c + 4]);
                mma8(sc[0][nt], a[0], bf);
                mma8(sc[1][nt], a[1], bf);
            }
        }

        // ---- exp (poly, FMA pipe), accumulate row sums, truncate to tf32 ----
        #pragma unroll
        for (int nt = 0; nt < 8; nt++) {
            float mf0 = smf[nt*8 + 2*c];
            float mf1 = smf[nt*8 + 2*c + 1];
            #pragma unroll
            for (int mt = 0; mt < 2; mt++) {
                float e0 = tf_trunc(exp_fast(fminf(fmaxf(sc[mt][nt][0] + mf0, -80.f), 60.f)));
                float e1 = tf_trunc(exp_fast(fminf(fmaxf(sc[mt][nt][1] + mf1, -80.f), 60.f)));
                float e2 = tf_trunc(exp_fast(fminf(fmaxf(sc[mt][nt][2] + mf0, -80.f), 60.f)));
                float e3 = tf_trunc(exp_fast(fminf(fmaxf(sc[mt][nt][3] + mf1, -80.f), 60.f)));
                lsum[mt][0] += e0 + e1;
                lsum[mt][1] += e2 + e3;
                sc[mt][nt][0] = e0; sc[mt][nt][1] = e1;
                sc[mt][nt][2] = e2; sc[mt][nt][3] = e3;
            }
        }

        // ---- P to smem (warp-private rows) ----
        #pragma unroll
        for (int mt = 0; mt < 2; mt++) {
            int row = wrow + mt * 16;
            #pragma unroll
            for (int nt = 0; nt < 8; nt++) {
                *(float2*)&Ps[(row + r    ) * AT_ST + nt*8 + 2*c] =
                    make_float2(sc[mt][nt][0], sc[mt][nt][1]);
                *(float2*)&Ps[(row + r + 8) * AT_ST + nt*8 + 2*c] =
                    make_float2(sc[mt][nt][2], sc[mt][nt][3]);
            }
        }
        __syncwarp();

        // ---- O += P V ----
        #pragma unroll
        for (int ks = 0; ks < 8; ks++) {
            unsigned a[2][4];
            #pragma unroll
            for (int mt = 0; mt < 2; mt++) {
                int row = wrow + mt * 16;
                a[mt][0] = __float_as_uint(Ps[(row + r    ) * AT_ST + ks*8 + c    ]);
                a[mt][1] = __float_as_uint(Ps[(row + r + 8) * AT_ST + ks*8 + c    ]);
                a[mt][2] = __float_as_uint(Ps[(row + r    ) * AT_ST + ks*8 + c + 4]);
                a[mt][3] = __float_as_uint(Ps[(row + r + 8) * AT_ST + ks*8 + c + 4]);
            }
            #pragma unroll
            for (int dt = 0; dt < 8; dt++) {
                unsigned bf[2];
                bf[0] = __float_as_uint(Vs[(ks*8 + c    ) * AT_ST + dt*8 + r]);
                bf[1] = __float_as_uint(Vs[(ks*8 + c + 4) * AT_ST + dt*8 + r]);
                mma8(oac[0][dt], a[0], bf);
                mma8(oac[1][dt], a[1], bf);
            }
        }
    }

    // ---- epilogue: normalize rows, fused mean via atomics ----
    #pragma unroll
    for (int mt = 0; mt < 2; mt++)
        #pragma unroll
        for (int j = 0; j < 2; j++) {
            float v = lsum[mt][j];
            v += __shfl_xor_sync(0xffffffffu, v, 1);
            v += __shfl_xor_sync(0xffffffffu, v, 2);
            lsum[mt][j] = 1.f / v;
        }

    const int h = bh & 15;
    #pragma unroll
    for (int dt = 0; dt < 8; dt++) {
        float p0 = oac[0][dt][0]*lsum[0][0] + oac[0][dt][2]*lsum[0][1]
                 + oac[1][dt][0]*lsum[1][0] + oac[1][dt][2]*lsum[1][1];
        float p1 = oac[0][dt][1]*lsum[0][0] + oac[0][dt][3]*lsum[0][1]
                 + oac[1][dt][1]*lsum[1][0] + oac[1][dt][3]*lsum[1][1];
        p0 += __shfl_xor_sync(0xffffffffu, p0, 4);
        p0 += __shfl_xor_sync(0xffffffffu, p0, 8);
        p0 += __shfl_xor_sync(0xffffffffu, p0, 16);
        p1 += __shfl_xor_sync(0xffffffffu, p1, 4);
        p1 += __shfl_xor_sync(0xffffffffu, p1, 8);
        p1 += __shfl_xor_sync(0xffffffffu, p1, 16);
        if (lane < 4) {
            atomicAdd(&g_pooled[b*E_ + h*64 + dt*8 + 2*c    ], p0);
            atomicAdd(&g_pooled[b*E_ + h*64 + dt*8 + 2*c + 1], p1);
        }
    }
}

// =====================================================================
// head A: o = (pooled/S) @ Wo^T + bo ; accumulate squared norm
// grid (128, B), 256 thr; warp per output column
// =====================================================================
__global__ __launch_bounds__(256) void headA_kernel(
    const float* __restrict__ Wo, const float* __restrict__ bo)
{
    const int b = blockIdx.y;
    const int n = blockIdx.x * 8 + (threadIdx.x >> 5);
    const int lane = threadIdx.x & 31;
    const float* pr = g_pooled + b * E_;
    const float* wr = Wo + (size_t)n * E_;
    float acc = 0.f;
    #pragma unroll
    for (int i = 0; i < 8; i++) {
        int k = i * 128 + lane * 4;
        float4 w = *(const float4*)(wr + k);
        float4 p = *(const float4*)(pr + k);
        acc += p.x*w.x + p.y*w.y + p.z*w.z + p.w*w.w;
    }
    #pragma unroll
    for (int off = 16; off > 0; off >>= 1)
        acc += __shfl_xor_sync(0xffffffffu, acc, off);
    if (lane == 0) {
        float o = acc * (1.0f / S_) + bo[n];
        g_o[b * E_ + n] = o;
        atomicAdd(&g_nrm[b], o * o);
    }
}

// =====================================================================
// head B: u = o/||o|| - text ; h = relu(u @ W1^T + b1) ; score += h*W2
// grid (64, B), 256 thr; warp per hidden row
// =====================================================================
__global__ __launch_bounds__(256) void headB_kernel(
    const float* __restrict__ text,
    const float* __restrict__ W1, const float* __restrict__ b1,
    const float* __restrict__ W2)
{
    const int b = blockIdx.y;
    const int rr = blockIdx.x * 8 + (threadIdx.x >> 5);
    const int lane = threadIdx.x & 31;
    const float rinv = rsqrtf(g_nrm[b]);
    const float* orow = g_o + b * E_;
    const float* trow = text + b * E_;
    const float* wr = W1 + (size_t)rr * E_;
    float acc = 0.f;
    #pragma unroll
    for (int i = 0; i < 8; i++) {
        int k = i * 128 + lane * 4;
        float4 w = *(const float4*)(wr + k);
        float4 o = *(const float4*)(orow + k);
        float4 t = *(const float4*)(trow + k);
        acc += (o.x*rinv - t.x)*w.x + (o.y*rinv - t.y)*w.y
             + (o.z*rinv - t.z)*w.z + (o.w*rinv - t.w)*w.w;
    }
    #pragma unroll
    for (int off = 16; off > 0; off >>= 1)
        acc += __shfl_xor_sync(0xffffffffu, acc, off);
    if (lane == 0) {
        float hv = fmaxf(acc + b1[rr], 0.f);
        atomicAdd(&g_score[b], hv * W2[rr]);
    }
}

__global__ void headC_kernel(const float* __restrict__ b2, float* __restrict__ out)
{
    int i = threadIdx.x;
    if (i < B_) out[i] = tanhf(g_score[i] + b2[0]);
}

// =====================================================================
// Launch
// =====================================================================
extern "C" void kernel_launch(void* const* d_in, const int* in_sizes, int n_in,
                              void* d_out, int out_size)
{
    (void)in_sizes; (void)n_in; (void)out_size;
    const float* x    = (const float*)d_in[0];
    const int*   mask = (const int*)  d_in[1];
    const float* text = (const float*)d_in[2];
    const float* Wq = (const float*)d_in[3];
    const float* bq = (const float*)d_in[4];
    const float* Wk = (const float*)d_in[5];
    const float* bk = (const float*)d_in[6];
    const float* Wv = (const float*)d_in[7];
    const float* bv = (const float*)d_in[8];
    const float* Wo = (const float*)d_in[9];
    const float* bo = (const float*)d_in[10];
    const float* W1 = (const float*)d_in[11];
    const float* b1 = (const float*)d_in[12];
    const float* W2 = (const float*)d_in[13];
    const float* b2 = (const float*)d_in[14];
    float* out = (float*)d_out;

    cudaFuncSetAttribute(attn_mma, cudaFuncAttributeMaxDynamicSharedMemorySize, ATTN_SMEM);

    zero_kernel<<<16, 256>>>();
    qkv_mma<<<dim3(8, 64, 3), 256>>>(x, Wq, bq, Wk, bk, Wv, bv);
    attn_mma<<<dim3(8, 64), 256, ATTN_SMEM>>>(mask);
    headA_kernel<<<dim3(128, B_), 256>>>(Wo, bo);
    headB_kernel<<<dim3(64, B_), 256>>>(text, W1, b1, W2);
    headC_kernel<<<1, 32>>>(b2, out);
}

// round 7
// speedup vs baseline: 1.0040x; 1.0007x over previous
#include <cuda_runtime.h>

// Problem constants
#define B_ 4
#define S_ 2048
#define E_ 1024
#define H_ 16
#define D_ 64

// ---------------- scratch ----------------
__device__ float g_Q[B_*H_*S_*D_];     // [B,H,S,D]
__device__ float g_K[B_*H_*S_*D_];
__device__ float g_V[B_*H_*S_*D_];
__device__ float g_pooled[B_*E_];      // column sums of attention output (pre mean-scale)
__device__ float g_o[B_*E_];           // out_proj output
__device__ float g_nrm[B_];            // squared norms
__device__ float g_score[B_];          // pre-tanh score

// ---------------- helpers ----------------
__device__ __forceinline__ unsigned f2tf(float x) {
    unsigned r; asm("cvt.rna.tf32.f32 %0, %1;" : "=r"(r) : "f"(x)); return r;
}
__device__ __forceinline__ float f2tff(float x) { return __uint_as_float(f2tf(x)); }

// D += A(m16k8,row) * B(k8n8,col), tf32
__device__ __forceinline__ void mma8(float* c, const unsigned* a, const unsigned* b) {
    asm("mma.sync.aligned.m16n8k8.row.col.f32.tf32.tf32.f32 "
        "{%0,%1,%2,%3}, {%4,%5,%6,%7}, {%8,%9}, {%0,%1,%2,%3};"
        : "+f"(c[0]), "+f"(c[1]), "+f"(c[2]), "+f"(c[3])
        : "r"(a[0]), "r"(a[1]), "r"(a[2]), "r"(a[3]), "r"(b[0]), "r"(b[1]));
}

// fast exp on the FMA/ALU pipes (input must already be clamped to [-80, 60])
__device__ __forceinline__ float exp_fast(float s) {
    float y = s * 1.4426950408889634f;
    float t = y + 12582912.f;             // round-to-nearest int via magic number
    float n = t - 12582912.f;
    float f = y - n;                      // f in [-0.5, 0.5]
    float p = fmaf(fmaf(fmaf(fmaf(0.009618130f, f,
                    0.05550411f), f, 0.2401597f), f, 0.6931472f), f, 1.0f);
    return __int_as_float(__float_as_int(p) + (__float_as_int(t) << 23));
}
// truncate fp32 to tf32 bit pattern (keeps P consistent between lsum and PV mma)
__device__ __forceinline__ float tf_trunc(float x) {
    return __uint_as_float(__float_as_uint(x) & 0xffffe000u);
}

// =====================================================================
// zero scratch accumulators
// =====================================================================
__global__ void zero_kernel() {
    int i = blockIdx.x * blockDim.x + threadIdx.x;
    if (i < B_*E_) g_pooled[i] = 0.f;
    if (i < B_) { g_nrm[i] = 0.f; g_score[i] = 0.f; }
}

// =====================================================================
// QKV projection via tf32 mma: Y = x @ W^T + b, scatter to [B,H,S,D]
// M=8192 N=1024 K=1024. BM=128 BN=128 BK=32, 256 threads (8 warps, 2x4),
// warp tile 64x32 (mt=4, nt=4).
// =====================================================================
__global__ __launch_bounds__(256) void qkv_mma(
    const float* __restrict__ x,
    const float* __restrict__ Wq, const float* __restrict__ bq,
    const float* __restrict__ Wk, const float* __restrict__ bk,
    const float* __restrict__ Wv, const float* __restrict__ bv)
{
    __shared__ __align__(16) float As[128][36];   // [m][k], pad->bank 4r+c conflict-free
    __shared__ __align__(16) float Bs[128][36];   // [n][k]

    const int z = blockIdx.z;
    const float* __restrict__ W    = (z == 0) ? Wq : ((z == 1) ? Wk : Wv);
    const float* __restrict__ bias = (z == 0) ? bq : ((z == 1) ? bk : bv);
    float* __restrict__ out        = (z == 0) ? g_Q : ((z == 1) ? g_K : g_V);

    const int tid  = threadIdx.x;
    const int lane = tid & 31, wid = tid >> 5;
    const int wm = wid >> 2, wn = wid & 3;
    const int m0 = blockIdx.y * 128, n0 = blockIdx.x * 128;
    const int r = lane >> 2, c = lane & 3;

    float acc[4][4][4];
    #pragma unroll
    for (int mt = 0; mt < 4; mt++)
        #pragma unroll
        for (int nt = 0; nt < 4; nt++)
            #pragma unroll
            for (int j = 0; j < 4; j++) acc[mt][nt][j] = 0.f;

    const int lr  = tid >> 3;         // 0..31
    const int lc4 = (tid & 7) * 4;    // 0..28

    for (int k0 = 0; k0 < E_; k0 += 32) {
        __syncthreads();
        #pragma unroll
        for (int it = 0; it < 4; it++) {
            int rr = lr + it * 32;
            float4 va = *(const float4*)(x + (size_t)(m0 + rr) * E_ + k0 + lc4);
            float4 vb = *(const float4*)(W + (size_t)(n0 + rr) * E_ + k0 + lc4);
            float4 sa, sb;
            sa.x = f2tff(va.x); sa.y = f2tff(va.y); sa.z = f2tff(va.z); sa.w = f2tff(va.w);
            sb.x = f2tff(vb.x); sb.y = f2tff(vb.y); sb.z = f2tff(vb.z); sb.w = f2tff(vb.w);
            *(float4*)&As[rr][lc4] = sa;
            *(float4*)&Bs[rr][lc4] = sb;
        }
        __syncthreads();

        #pragma unroll
        for (int ks = 0; ks < 4; ks++) {
            unsigned a[4][4];
            #pragma unroll
            for (int mt = 0; mt < 4; mt++) {
                int row = wm * 64 + mt * 16;
                a[mt][0] = __float_as_uint(As[row + r    ][ks*8 + c    ]);
                a[mt][1] = __float_as_uint(As[row + r + 8][ks*8 + c    ]);
                a[mt][2] = __float_as_uint(As[row + r    ][ks*8 + c + 4]);
                a[mt][3] = __float_as_uint(As[row + r + 8][ks*8 + c + 4]);
            }
            #pragma unroll
            for (int nt = 0; nt < 4; nt++) {
                int col = wn * 32 + nt * 8;
                unsigned bf[2];
                bf[0] = __float_as_uint(Bs[col + r][ks*8 + c    ]);
                bf[1] = __float_as_uint(Bs[col + r][ks*8 + c + 4]);
                #pragma unroll
                for (int mt = 0; mt < 4; mt++) mma8(acc[mt][nt], a[mt], bf);
            }
        }
    }

    // epilogue: bias + scatter to [B,H,S,D]
    #pragma unroll
    for (int nt = 0; nt < 4; nt++) {
        int coln = n0 + wn * 32 + nt * 8 + 2 * c;
        int h = coln >> 6, d = coln & 63;
        float bv0 = bias[coln], bv1 = bias[coln + 1];
        #pragma unroll
        for (int mt = 0; mt < 4; mt++) {
            int gm = m0 + wm * 64 + mt * 16 + r;
            int bb = gm >> 11, s = gm & (S_ - 1);
            float2 v0 = make_float2(acc[mt][nt][0] + bv0, acc[mt][nt][1] + bv1);
            float2 v1 = make_float2(acc[mt][nt][2] + bv0, acc[mt][nt][3] + bv1);
            *(float2*)(out + (size_t)((bb*H_ + h)*S_ + s    ) * D_ + d) = v0;
            *(float2*)(out + (size_t)((bb*H_ + h)*S_ + s + 8) * D_ + d) = v1;
        }
    }
}

// =====================================================================
// Flash attention via tf32 mma, no-max softmax with polynomial exp.
// Block: 256 query rows (8 warps x 32 rows, mt=2), key tile 64.
// Fuses the mean-over-S via atomicAdd into g_pooled.
// =====================================================================
#define AT_ST 68    // padded row stride -> banks 4r+c, conflict-free frag loads
#define ATTN_SMEM ((256 + 64 + 64 + 256) * AT_ST * 4 + 64 * 4)

__global__ __launch_bounds__(256) void attn_mma(const int* __restrict__ mask)
{
    extern __shared__ __align__(16) float sm[];
    float* Qs = sm;                        // [256][AT_ST] tf32, pre-scaled
    float* Ks = Qs + 256 * AT_ST;          // [64][AT_ST]  tf32
    float* Vs = Ks + 64 * AT_ST;           // [64][AT_ST]  tf32
    float* Ps = Vs + 64 * AT_ST;           // [256][AT_ST] tf32 (truncated exp)
    float* smf = Ps + 256 * AT_ST;         // [64] mask add (-1e9 / 0)

    const int tid  = threadIdx.x;
    const int lane = tid & 31, wid = tid >> 5;
    const int bh = blockIdx.y, b = bh >> 4;
    const int m0 = blockIdx.x * 256;
    const int r = lane >> 2, c = lane & 3;
    const int wrow = wid * 32;

    const float* Qg = g_Q + (size_t)(bh * S_ + m0) * D_;
    const float* Kg = g_K + (size_t)bh * S_ * D_;
    const float* Vg = g_V + (size_t)bh * S_ * D_;

    // Q tile (fold 1/sqrt(D), convert tf32)
    #pragma unroll
    for (int it = 0; it < 16; it++) {
        int lin = tid + it * 256;
        int rr = lin >> 4, c4 = (lin & 15) * 4;
        float4 v = *(const float4*)(Qg + (size_t)rr * D_ + c4);
        float4 sv;
        sv.x = f2tff(v.x * 0.125f); sv.y = f2tff(v.y * 0.125f);
        sv.z = f2tff(v.z * 0.125f); sv.w = f2tff(v.w * 0.125f);
        *(float4*)&Qs[rr * AT_ST + c4] = sv;
    }

    float oac[2][8][4];
    #pragma unroll
    for (int mt = 0; mt < 2; mt++)
        #pragma unroll
        for (int dt = 0; dt < 8; dt++)
            #pragma unroll
            for (int j = 0; j < 4; j++) oac[mt][dt][j] = 0.f;
    float lsum[2][2] = {{0.f, 0.f}, {0.f, 0.f}};

    for (int n0 = 0; n0 < S_; n0 += 64) {
        __syncthreads();
        #pragma unroll
        for (int it = 0; it < 4; it++) {
            int lin = tid + it * 256;
            int rr = lin >> 4, c4 = (lin & 15) * 4;
            float4 kv = *(const float4*)(Kg + (size_t)(n0 + rr) * D_ + c4);
            float4 vv = *(const float4*)(Vg + (size_t)(n0 + rr) * D_ + c4);
            float4 sk, sv;
            sk.x = f2tff(kv.x); sk.y = f2tff(kv.y); sk.z = f2tff(kv.z); sk.w = f2tff(kv.w);
            sv.x = f2tff(vv.x); sv.y = f2tff(vv.y); sv.z = f2tff(vv.z); sv.w = f2tff(vv.w);
            *(float4*)&Ks[rr * AT_ST + c4] = sk;
            *(float4*)&Vs[rr * AT_ST + c4] = sv;
        }
        if (tid < 64) smf[tid] = mask[b * S_ + n0 + tid] ? 0.f : -1e9f;
        __syncthreads();

        // ---- S = Q K^T ----
        float sc[2][8][4];
        #pragma unroll
        for (int mt = 0; mt < 2; mt++)
            #pragma unroll
            for (int nt = 0; nt < 8; nt++)
                #pragma unroll
                for (int j = 0; j < 4; j++) sc[mt][nt][j] = 0.f;

        #pragma unroll
        for (int ks = 0; ks < 8; ks++) {
            unsigned a[2][4];
            #pragma unroll
            for (int mt = 0; mt < 2; mt++) {
                int row = wrow + mt * 16;
                a[mt][0] = __float_as_uint(Qs[(row + r    ) * AT_ST + ks*8 + c    ]);
                a[mt][1] = __float_as_uint(Qs[(row + r + 8) * AT_ST + ks*8 + c    ]);
                a[mt][2] = __float_as_uint(Qs[(row + r    ) * AT_ST + ks*8 + c + 4]);
                a[mt][3] = __float_as_uint(Qs[(row + r + 8) * AT_ST + ks*8 + c + 4]);
            }
            #pragma unroll
            for (int nt = 0; nt < 8; nt++) {
                unsigned bf[2];
                bf[0] = __float_as_uint(Ks[(nt*8 + r) * AT_ST + ks*8 + c    ]);
                bf[1] = __float_as_uint(Ks[(nt*8 + r) * AT_ST + ks*8 + c + 4]);
                mma8(sc[0][nt], a[0], bf);
                mma8(sc[1][nt], a[1], bf);
            }
        }

        // ---- exp (poly, FMA pipe), accumulate row sums, truncate to tf32 ----
        #pragma unroll
        for (int nt = 0; nt < 8; nt++) {
            float mf0 = smf[nt*8 + 2*c];
            float mf1 = smf[nt*8 + 2*c + 1];
            #pragma unroll
            for (int mt = 0; mt < 2; mt++) {
                float e0 = tf_trunc(exp_fast(fminf(fmaxf(sc[mt][nt][0] + mf0, -80.f), 60.f)));
                float e1 = tf_trunc(exp_fast(fminf(fmaxf(sc[mt][nt][1] + mf1, -80.f), 60.f)));
                float e2 = tf_trunc(exp_fast(fminf(fmaxf(sc[mt][nt][2] + mf0, -80.f), 60.f)));
                float e3 = tf_trunc(exp_fast(fminf(fmaxf(sc[mt][nt][3] + mf1, -80.f), 60.f)));
                lsum[mt][0] += e0 + e1;
                lsum[mt][1] += e2 + e3;
                sc[mt][nt][0] = e0; sc[mt][nt][1] = e1;
                sc[mt][nt][2] = e2; sc[mt][nt][3] = e3;
            }
        }

        // ---- P to smem (warp-private rows) ----
        #pragma unroll
        for (int mt = 0; mt < 2; mt++) {
            int row = wrow + mt * 16;
            #pragma unroll
            for (int nt = 0; nt < 8; nt++) {
                *(float2*)&Ps[(row + r    ) * AT_ST + nt*8 + 2*c] =
                    make_float2(sc[mt][nt][0], sc[mt][nt][1]);
                *(float2*)&Ps[(row + r + 8) * AT_ST + nt*8 + 2*c] =
                    make_float2(sc[mt][nt][2], sc[mt][nt][3]);
            }
        }
        __syncwarp();

        // ---- O += P V ----
        #pragma unroll
        for (int ks = 0; ks < 8; ks++) {
            unsigned a[2][4];
            #pragma unroll
            for (int mt = 0; mt < 2; mt++) {
                int row = wrow + mt * 16;
                a[mt][0] = __float_as_uint(Ps[(row + r    ) * AT_ST + ks*8 + c    ]);
                a[mt][1] = __float_as_uint(Ps[(row + r + 8) * AT_ST + ks*8 + c    ]);
                a[mt][2] = __float_as_uint(Ps[(row + r    ) * AT_ST + ks*8 + c + 4]);
                a[mt][3] = __float_as_uint(Ps[(row + r + 8) * AT_ST + ks*8 + c + 4]);
            }
            #pragma unroll
            for (int dt = 0; dt < 8; dt++) {
                unsigned bf[2];
                bf[0] = __float_as_uint(Vs[(ks*8 + c    ) * AT_ST + dt*8 + r]);
                bf[1] = __float_as_uint(Vs[(ks*8 + c + 4) * AT_ST + dt*8 + r]);
                mma8(oac[0][dt], a[0], bf);
                mma8(oac[1][dt], a[1], bf);
            }
        }
    }

    // ---- epilogue: normalize rows, fused mean via atomics ----
    #pragma unroll
    for (int mt = 0; mt < 2; mt++)
        #pragma unroll
        for (int j = 0; j < 2; j++) {
            float v = lsum[mt][j];
            v += __shfl_xor_sync(0xffffffffu, v, 1);
            v += __shfl_xor_sync(0xffffffffu, v, 2);
            lsum[mt][j] = 1.f / v;
        }

    const int h = bh & 15;
    #pragma unroll
    for (int dt = 0; dt < 8; dt++) {
        float p0 = oac[0][dt][0]*lsum[0][0] + oac[0][dt][2]*lsum[0][1]
                 + oac[1][dt][0]*lsum[1][0] + oac[1][dt][2]*lsum[1][1];
        float p1 = oac[0][dt][1]*lsum[0][0] + oac[0][dt][3]*lsum[0][1]
                 + oac[1][dt][1]*lsum[1][0] + oac[1][dt][3]*lsum[1][1];
        p0 += __shfl_xor_sync(0xffffffffu, p0, 4);
        p0 += __shfl_xor_sync(0xffffffffu, p0, 8);
        p0 += __shfl_xor_sync(0xffffffffu, p0, 16);
        p1 += __shfl_xor_sync(0xffffffffu, p1, 4);
        p1 += __shfl_xor_sync(0xffffffffu, p1, 8);
        p1 += __shfl_xor_sync(0xffffffffu, p1, 16);
        if (lane < 4) {
            atomicAdd(&g_pooled[b*E_ + h*64 + dt*8 + 2*c    ], p0);
            atomicAdd(&g_pooled[b*E_ + h*64 + dt*8 + 2*c + 1], p1);
        }
    }
}

// =====================================================================
// head A: o = (pooled/S) @ Wo^T + bo ; accumulate squared norm
// grid (128, B), 256 thr; warp per output column
// =====================================================================
__global__ __launch_bounds__(256) void headA_kernel(
    const float* __restrict__ Wo, const float* __restrict__ bo)
{
    const int b = blockIdx.y;
    const int n = blockIdx.x * 8 + (threadIdx.x >> 5);
    const int lane = threadIdx.x & 31;
    const float* pr = g_pooled + b * E_;
    const float* wr = Wo + (size_t)n * E_;
    float acc = 0.f;
    #pragma unroll
    for (int i = 0; i < 8; i++) {
        int k = i * 128 + lane * 4;
        float4 w = *(const float4*)(wr + k);
        float4 p = *(const float4*)(pr + k);
        acc += p.x*w.x + p.y*w.y + p.z*w.z + p.w*w.w;
    }
    #pragma unroll
    for (int off = 16; off > 0; off >>= 1)
        acc += __shfl_xor_sync(0xffffffffu, acc, off);
    if (lane == 0) {
        float o = acc * (1.0f / S_) + bo[n];
        g_o[b * E_ + n] = o;
        atomicAdd(&g_nrm[b], o * o);
    }
}

// =====================================================================
// head B: u = o/||o|| - text ; h = relu(u @ W1^T + b1) ; score += h*W2
// grid (64, B), 256 thr; warp per hidden row
// =====================================================================
__global__ __launch_bounds__(256) void headB_kernel(
    const float* __restrict__ text,
    const float* __restrict__ W1, const float* __restrict__ b1,
    const float* __restrict__ W2)
{
    const int b = blockIdx.y;
    const int rr = blockIdx.x * 8 + (threadIdx.x >> 5);
    const int lane = threadIdx.x & 31;
    const float rinv = rsqrtf(g_nrm[b]);
    const float* orow = g_o + b * E_;
    const float* trow = text + b * E_;
    const float* wr = W1 + (size_t)rr * E_;
    float acc = 0.f;
    #pragma unroll
    for (int i = 0; i < 8; i++) {
        int k = i * 128 + lane * 4;
        float4 w = *(const float4*)(wr + k);
        float4 o = *(const float4*)(orow + k);
        float4 t = *(const float4*)(trow + k);
        acc += (o.x*rinv - t.x)*w.x + (o.y*rinv - t.y)*w.y
             + (o.z*rinv - t.z)*w.z + (o.w*rinv - t.w)*w.w;
    }
    #pragma unroll
    for (int off = 16; off > 0; off >>= 1)
        acc += __shfl_xor_sync(0xffffffffu, acc, off);
    if (lane == 0) {
        float hv = fmaxf(acc + b1[rr], 0.f);
        atomicAdd(&g_score[b], hv * W2[rr]);
    }
}

__global__ void headC_kernel(const float* __restrict__ b2, float* __restrict__ out)
{
    int i = threadIdx.x;
    if (i < B_) out[i] = tanhf(g_score[i] + b2[0]);
}

// =====================================================================
// Launch
// =====================================================================
extern "C" void kernel_launch(void* const* d_in, const int* in_sizes, int n_in,
                              void* d_out, int out_size)
{
    (void)in_sizes; (void)n_in; (void)out_size;
    const float* x    = (const float*)d_in[0];
    const int*   mask = (const int*)  d_in[1];
    const float* text = (const float*)d_in[2];
    const float* Wq = (const float*)d_in[3];
    const float* bq = (const float*)d_in[4];
    const float* Wk = (const float*)d_in[5];
    const float* bk = (const float*)d_in[6];
    const float* Wv = (const float*)d_in[7];
    const float* bv = (const float*)d_in[8];
    const float* Wo = (const float*)d_in[9];
    const float* bo = (const float*)d_in[10];
    const float* W1 = (const float*)d_in[11];
    const float* b1 = (const float*)d_in[12];
    const float* W2 = (const float*)d_in[13];
    const float* b2 = (const float*)d_in[14];
    float* out = (float*)d_out;

    cudaFuncSetAttribute(attn_mma, cudaFuncAttributeMaxDynamicSharedMemorySize, ATTN_SMEM);

    zero_kernel<<<16, 256>>>();
    qkv_mma<<<dim3(8, 64, 3), 256>>>(x, Wq, bq, Wk, bk, Wv, bv);
    attn_mma<<<dim3(8, 64), 256, ATTN_SMEM>>>(mask);
    headA_kernel<<<dim3(128, B_), 256>>>(Wo, bo);
    headB_kernel<<<dim3(64, B_), 256>>>(text, W1, b1, W2);
    headC_kernel<<<1, 32>>>(b2, out);
}

// round 8
// speedup vs baseline: 1.3913x; 1.3857x over previous
#include <cuda_runtime.h>
#include <cuda_bf16.h>

// Problem constants
#define B_ 4
#define S_ 2048
#define E_ 1024
#define H_ 16
#define D_ 64

// ---------------- scratch ----------------
__device__ float g_Q[B_*H_*S_*D_];     // [B,H,S,D]
__device__ float g_K[B_*H_*S_*D_];
__device__ float g_V[B_*H_*S_*D_];
__device__ float g_pooled[B_*E_];      // column sums of attention output (pre mean-scale)
__device__ float g_o[B_*E_];           // out_proj output
__device__ float g_nrm[B_];            // squared norms
__device__ float g_score[B_];          // pre-tanh score

// ---------------- helpers ----------------
// D += A(m16k16,row) * B(k16n8,col), bf16 in, fp32 accum
__device__ __forceinline__ void mma16(float* c, const unsigned* a, const unsigned* b) {
    asm("mma.sync.aligned.m16n8k16.row.col.f32.bf16.bf16.f32 "
        "{%0,%1,%2,%3}, {%4,%5,%6,%7}, {%8,%9}, {%0,%1,%2,%3};"
        : "+f"(c[0]), "+f"(c[1]), "+f"(c[2]), "+f"(c[3])
        : "r"(a[0]), "r"(a[1]), "r"(a[2]), "r"(a[3]), "r"(b[0]), "r"(b[1]));
}
__device__ __forceinline__ unsigned pack_bf2(float lo, float hi) {
    __nv_bfloat162 h = __floats2bfloat162_rn(lo, hi);   // .x = lo
    return *reinterpret_cast<unsigned*>(&h);
}
__device__ __forceinline__ float ex2f(float x) {
    float r; asm("ex2.approx.f32 %0, %1;" : "=f"(r) : "f"(x)); return r;
}

// =====================================================================
// zero scratch accumulators
// =====================================================================
__global__ void zero_kernel() {
    int i = blockIdx.x * blockDim.x + threadIdx.x;
    if (i < B_*E_) g_pooled[i] = 0.f;
    if (i < B_) { g_nrm[i] = 0.f; g_score[i] = 0.f; }
}

// =====================================================================
// QKV projection via bf16 mma: Y = x @ W^T + b, scatter to [B,H,S,D]
// M=8192 N=1024 K=1024. BM=128 BN=128 BK=32, 256 threads (8 warps, 2x4),
// warp tile 64x32 (mt=4, nt=4), m16n8k16.
// =====================================================================
#define QST 72   // bf16 row stride (144B): frag-load bank pattern 4g+t, conflict-free

__global__ __launch_bounds__(256) void qkv_mma(
    const float* __restrict__ x,
    const float* __restrict__ Wq, const float* __restrict__ bq,
    const float* __restrict__ Wk, const float* __restrict__ bk,
    const float* __restrict__ Wv, const float* __restrict__ bv)
{
    __shared__ __align__(16) __nv_bfloat16 As[128][QST];   // [m][k]
    __shared__ __align__(16) __nv_bfloat16 Bs[128][QST];   // [n][k]

    const int z = blockIdx.z;
    const float* __restrict__ W    = (z == 0) ? Wq : ((z == 1) ? Wk : Wv);
    const float* __restrict__ bias = (z == 0) ? bq : ((z == 1) ? bk : bv);
    float* __restrict__ out        = (z == 0) ? g_Q : ((z == 1) ? g_K : g_V);

    const int tid  = threadIdx.x;
    const int lane = tid & 31, wid = tid >> 5;
    const int wm = wid >> 2, wn = wid & 3;
    const int m0 = blockIdx.y * 128, n0 = blockIdx.x * 128;
    const int g = lane >> 2, t = lane & 3;

    float acc[4][4][4];
    #pragma unroll
    for (int mt = 0; mt < 4; mt++)
        #pragma unroll
        for (int nt = 0; nt < 4; nt++)
            #pragma unroll
            for (int j = 0; j < 4; j++) acc[mt][nt][j] = 0.f;

    const int lr  = tid >> 3;         // 0..31
    const int lc4 = (tid & 7) * 4;    // 0..28

    for (int k0 = 0; k0 < E_; k0 += 32) {
        __syncthreads();
        #pragma unroll
        for (int it = 0; it < 4; it++) {
            int rr = lr + it * 32;
            float4 va = *(const float4*)(x + (size_t)(m0 + rr) * E_ + k0 + lc4);
            float4 vb = *(const float4*)(W + (size_t)(n0 + rr) * E_ + k0 + lc4);
            uint2 ua = make_uint2(pack_bf2(va.x, va.y), pack_bf2(va.z, va.w));
            uint2 ub = make_uint2(pack_bf2(vb.x, vb.y), pack_bf2(vb.z, vb.w));
            *(uint2*)&As[rr][lc4] = ua;
            *(uint2*)&Bs[rr][lc4] = ub;
        }
        __syncthreads();

        #pragma unroll
        for (int ks = 0; ks < 2; ks++) {
            unsigned a[4][4];
            #pragma unroll
            for (int mt = 0; mt < 4; mt++) {
                int row = wm * 64 + mt * 16;
                a[mt][0] = *(const unsigned*)&As[row + g    ][ks*16 + 2*t    ];
                a[mt][1] = *(const unsigned*)&As[row + g + 8][ks*16 + 2*t    ];
                a[mt][2] = *(const unsigned*)&As[row + g    ][ks*16 + 2*t + 8];
                a[mt][3] = *(const unsigned*)&As[row + g + 8][ks*16 + 2*t + 8];
            }
            #pragma unroll
            for (int nt = 0; nt < 4; nt++) {
                int col = wn * 32 + nt * 8;
                unsigned bf[2];
                bf[0] = *(const unsigned*)&Bs[col + g][ks*16 + 2*t    ];
                bf[1] = *(const unsigned*)&Bs[col + g][ks*16 + 2*t + 8];
                #pragma unroll
                for (int mt = 0; mt < 4; mt++) mma16(acc[mt][nt], a[mt], bf);
            }
        }
    }

    // epilogue: bias + scatter to [B,H,S,D]
    #pragma unroll
    for (int nt = 0; nt < 4; nt++) {
        int coln = n0 + wn * 32 + nt * 8 + 2 * t;
        int h = coln >> 6, d = coln & 63;
        float bv0 = bias[coln], bv1 = bias[coln + 1];
        #pragma unroll
        for (int mt = 0; mt < 4; mt++) {
            int gm = m0 + wm * 64 + mt * 16 + g;
            int bb = gm >> 11, s = gm & (S_ - 1);
            float2 v0 = make_float2(acc[mt][nt][0] + bv0, acc[mt][nt][1] + bv1);
            float2 v1 = make_float2(acc[mt][nt][2] + bv0, acc[mt][nt][3] + bv1);
            *(float2*)(out + (size_t)((bb*H_ + h)*S_ + s    ) * D_ + d) = v0;
            *(float2*)(out + (size_t)((bb*H_ + h)*S_ + s + 8) * D_ + d) = v1;
        }
    }
}

// =====================================================================
// Flash attention via bf16 mma + ex2.approx softmax (log2-domain, no max).
// Block: 128 query rows (8 warps x 16 rows), key tile 64. 2 blocks/SM.
// Q prescaled by 0.125*log2e so QK^T scores are already log2-domain.
// Fuses mean-over-S: block-local smem reduction, then 64 atomics.
// =====================================================================
#define AST 72
#define ATTN_SMEM ((128 + 64 + 64 + 128) * AST * 2 + 64 * 4 + 64 * 4)

__global__ __launch_bounds__(256) void attn_mma(const int* __restrict__ mask)
{
    extern __shared__ __align__(16) char smraw[];
    __nv_bfloat16* Qs = (__nv_bfloat16*)smraw;     // [128][AST] bf16, prescaled
    __nv_bfloat16* Ks = Qs + 128 * AST;            // [64][AST]  key-major
    __nv_bfloat16* Vt = Ks + 64 * AST;             // [64][AST]  d-major (transposed)
    __nv_bfloat16* Ps = Vt + 64 * AST;             // [128][AST] bf16 exp scores
    float* smf   = (float*)(Ps + 128 * AST);       // [64] mask add (log2 dom)
    float* spool = smf + 64;                       // [64] block-local pooled sums

    const int tid  = threadIdx.x;
    const int lane = tid & 31, wid = tid >> 5;
    const int g = lane >> 2, t = lane & 3;
    const int wrow = wid * 16;
    const int bh = blockIdx.y, b = bh >> 4;
    const int m0 = blockIdx.x * 128;

    const float* Qg = g_Q + (size_t)(bh * S_ + m0) * D_;
    const float* Kg = g_K + (size_t)bh * S_ * D_;
    const float* Vg = g_V + (size_t)bh * S_ * D_;

    const float QSC = 0.125f * 1.4426950408889634f;   // 1/sqrt(D) * log2(e)

    // Q tile: fold scale, convert bf16
    #pragma unroll
    for (int it = 0; it < 8; it++) {
        int lin = tid + it * 256;               // 0..2047
        int rr = lin >> 4, c4 = (lin & 15) * 4;
        float4 v = *(const float4*)(Qg + (size_t)rr * D_ + c4);
        uint2 u = make_uint2(pack_bf2(v.x * QSC, v.y * QSC),
                             pack_bf2(v.z * QSC, v.w * QSC));
        *(uint2*)&Qs[rr * AST + c4] = u;
    }
    if (tid < 64) spool[tid] = 0.f;

    float oac[8][4];
    #pragma unroll
    for (int dt = 0; dt < 8; dt++)
        #pragma unroll
        for (int j = 0; j < 4; j++) oac[dt][j] = 0.f;
    float lsum0 = 0.f, lsum1 = 0.f;

    for (int n0t = 0; n0t < S_; n0t += 64) {
        __syncthreads();
        // K tile (key-major rows)
        #pragma unroll
        for (int it = 0; it < 4; it++) {
            int lin = tid + it * 256;           // 0..1023
            int rr = lin >> 4, c4 = (lin & 15) * 4;
            float4 kv = *(const float4*)(Kg + (size_t)(n0t + rr) * D_ + c4);
            *(uint2*)&Ks[rr * AST + c4] =
                make_uint2(pack_bf2(kv.x, kv.y), pack_bf2(kv.z, kv.w));
        }
        // V tile transposed to d-major
        #pragma unroll
        for (int it = 0; it < 4; it++) {
            int lin = tid + it * 256;
            int d = lin & 63, k4 = (lin >> 6) * 4;
            float v0 = Vg[(size_t)(n0t + k4 + 0) * D_ + d];
            float v1 = Vg[(size_t)(n0t + k4 + 1) * D_ + d];
            float v2 = Vg[(size_t)(n0t + k4 + 2) * D_ + d];
            float v3 = Vg[(size_t)(n0t + k4 + 3) * D_ + d];
            *(uint2*)&Vt[d * AST + k4] =
                make_uint2(pack_bf2(v0, v1), pack_bf2(v2, v3));
        }
        if (tid < 64) smf[tid] = mask[b * S_ + n0t + tid] ? 0.f : -1e9f;
        __syncthreads();

        // ---- S = Q K^T (log2 domain) ----
        float sc[8][4];
        #pragma unroll
        for (int nt = 0; nt < 8; nt++)
            #pragma unroll
            for (int j = 0; j < 4; j++) sc[nt][j] = 0.f;

        #pragma unroll
        for (int ks = 0; ks < 4; ks++) {
            unsigned a[4];
            a[0] = *(const unsigned*)&Qs[(wrow + g    ) * AST + ks*16 + 2*t    ];
            a[1] = *(const unsigned*)&Qs[(wrow + g + 8) * AST + ks*16 + 2*t    ];
            a[2] = *(const unsigned*)&Qs[(wrow + g    ) * AST + ks*16 + 2*t + 8];
            a[3] = *(const unsigned*)&Qs[(wrow + g + 8) * AST + ks*16 + 2*t + 8];
            #pragma unroll
            for (int nt = 0; nt < 8; nt++) {
                unsigned bf[2];
                bf[0] = *(const unsigned*)&Ks[(nt*8 + g) * AST + ks*16 + 2*t    ];
                bf[1] = *(const unsigned*)&Ks[(nt*8 + g) * AST + ks*16 + 2*t + 8];
                mma16(sc[nt], a, bf);
            }
        }

        // ---- exp via MUFU ex2 (masked keys underflow to 0), pack bf16 ----
        #pragma unroll
        for (int nt = 0; nt < 8; nt++) {
            float mf0 = smf[nt*8 + 2*t], mf1 = smf[nt*8 + 2*t + 1];
            float e0 = ex2f(sc[nt][0] + mf0);
            float e1 = ex2f(sc[nt][1] + mf1);
            float e2 = ex2f(sc[nt][2] + mf0);
            float e3 = ex2f(sc[nt][3] + mf1);
            lsum0 += e0 + e1;
            lsum1 += e2 + e3;
            *(unsigned*)&Ps[(wrow + g    ) * AST + nt*8 + 2*t] = pack_bf2(e0, e1);
            *(unsigned*)&Ps[(wrow + g + 8) * AST + nt*8 + 2*t] = pack_bf2(e2, e3);
        }
        __syncwarp();

        // ---- O += P V ----
        #pragma unroll
        for (int ks = 0; ks < 4; ks++) {
            unsigned a[4];
            a[0] = *(const unsigned*)&Ps[(wrow + g    ) * AST + ks*16 + 2*t    ];
            a[1] = *(const unsigned*)&Ps[(wrow + g + 8) * AST + ks*16 + 2*t    ];
            a[2] = *(const unsigned*)&Ps[(wrow + g    ) * AST + ks*16 + 2*t + 8];
            a[3] = *(const unsigned*)&Ps[(wrow + g + 8) * AST + ks*16 + 2*t + 8];
            #pragma unroll
            for (int dt = 0; dt < 8; dt++) {
                unsigned bf[2];
                bf[0] = *(const unsigned*)&Vt[(dt*8 + g) * AST + ks*16 + 2*t    ];
                bf[1] = *(const unsigned*)&Vt[(dt*8 + g) * AST + ks*16 + 2*t + 8];
                mma16(oac[dt], a, bf);
            }
        }
    }

    // ---- epilogue: normalize rows, block-local pooled reduction ----
    lsum0 += __shfl_xor_sync(0xffffffffu, lsum0, 1);
    lsum0 += __shfl_xor_sync(0xffffffffu, lsum0, 2);
    lsum1 += __shfl_xor_sync(0xffffffffu, lsum1, 1);
    lsum1 += __shfl_xor_sync(0xffffffffu, lsum1, 2);
    float inv0 = 1.f / lsum0, inv1 = 1.f / lsum1;

    #pragma unroll
    for (int dt = 0; dt < 8; dt++) {
        float p0 = oac[dt][0] * inv0 + oac[dt][2] * inv1;
        float p1 = oac[dt][1] * inv0 + oac[dt][3] * inv1;
        p0 += __shfl_xor_sync(0xffffffffu, p0, 4);
        p0 += __shfl_xor_sync(0xffffffffu, p0, 8);
        p0 += __shfl_xor_sync(0xffffffffu, p0, 16);
        p1 += __shfl_xor_sync(0xffffffffu, p1, 4);
        p1 += __shfl_xor_sync(0xffffffffu, p1, 8);
        p1 += __shfl_xor_sync(0xffffffffu, p1, 16);
        if (lane < 4) {
            atomicAdd(&spool[dt*8 + 2*t    ], p0);
            atomicAdd(&spool[dt*8 + 2*t + 1], p1);
        }
    }
    __syncthreads();
    if (tid < 64) {
        const int h = bh & 15;
        atomicAdd(&g_pooled[b*E_ + h*64 + tid], spool[tid]);
    }
}

// =====================================================================
// head A: o = (pooled/S) @ Wo^T + bo ; accumulate squared norm
// =====================================================================
__global__ __launch_bounds__(256) void headA_kernel(
    const float* __restrict__ Wo, const float* __restrict__ bo)
{
    const int b = blockIdx.y;
    const int n = blockIdx.x * 8 + (threadIdx.x >> 5);
    const int lane = threadIdx.x & 31;
    const float* pr = g_pooled + b * E_;
    const float* wr = Wo + (size_t)n * E_;
    float acc = 0.f;
    #pragma unroll
    for (int i = 0; i < 8; i++) {
        int k = i * 128 + lane * 4;
        float4 w = *(const float4*)(wr + k);
        float4 p = *(const float4*)(pr + k);
        acc += p.x*w.x + p.y*w.y + p.z*w.z + p.w*w.w;
    }
    #pragma unroll
    for (int off = 16; off > 0; off >>= 1)
        acc += __shfl_xor_sync(0xffffffffu, acc, off);
    if (lane == 0) {
        float o = acc * (1.0f / S_) + bo[n];
        g_o[b * E_ + n] = o;
        atomicAdd(&g_nrm[b], o * o);
    }
}

// =====================================================================
// head B: u = o/||o|| - text ; h = relu(u @ W1^T + b1) ; score += h*W2
// =====================================================================
__global__ __launch_bounds__(256) void headB_kernel(
    const float* __restrict__ text,
    const float* __restrict__ W1, const float* __restrict__ b1,
    const float* __restrict__ W2)
{
    const int b = blockIdx.y;
    const int rr = blockIdx.x * 8 + (threadIdx.x >> 5);
    const int lane = threadIdx.x & 31;
    const float rinv = rsqrtf(g_nrm[b]);
    const float* orow = g_o + b * E_;
    const float* trow = text + b * E_;
    const float* wr = W1 + (size_t)rr * E_;
    float acc = 0.f;
    #pragma unroll
    for (int i = 0; i < 8; i++) {
        int k = i * 128 + lane * 4;
        float4 w = *(const float4*)(wr + k);
        float4 o = *(const float4*)(orow + k);
        float4 tt = *(const float4*)(trow + k);
        acc += (o.x*rinv - tt.x)*w.x + (o.y*rinv - tt.y)*w.y
             + (o.z*rinv - tt.z)*w.z + (o.w*rinv - tt.w)*w.w;
    }
    #pragma unroll
    for (int off = 16; off > 0; off >>= 1)
        acc += __shfl_xor_sync(0xffffffffu, acc, off);
    if (lane == 0) {
        float hv = fmaxf(acc + b1[rr], 0.f);
        atomicAdd(&g_score[b], hv * W2[rr]);
    }
}

__global__ void headC_kernel(const float* __restrict__ b2, float* __restrict__ out)
{
    int i = threadIdx.x;
    if (i < B_) out[i] = tanhf(g_score[i] + b2[0]);
}

// =====================================================================
// Launch
// =====================================================================
extern "C" void kernel_launch(void* const* d_in, const int* in_sizes, int n_in,
                              void* d_out, int out_size)
{
    (void)in_sizes; (void)n_in; (void)out_size;
    const float* x    = (const float*)d_in[0];
    const int*   mask = (const int*)  d_in[1];
    const float* text = (const float*)d_in[2];
    const float* Wq = (const float*)d_in[3];
    const float* bq = (const float*)d_in[4];
    const float* Wk = (const float*)d_in[5];
    const float* bk = (const float*)d_in[6];
    const float* Wv = (const float*)d_in[7];
    const float* bv = (const float*)d_in[8];
    const float* Wo = (const float*)d_in[9];
    const float* bo = (const float*)d_in[10];
    const float* W1 = (const float*)d_in[11];
    const float* b1 = (const float*)d_in[12];
    const float* W2 = (const float*)d_in[13];
    const float* b2 = (const float*)d_in[14];
    float* out = (float*)d_out;

    cudaFuncSetAttribute(attn_mma, cudaFuncAttributeMaxDynamicSharedMemorySize, ATTN_SMEM);

    zero_kernel<<<16, 256>>>();
    qkv_mma<<<dim3(8, 64, 3), 256>>>(x, Wq, bq, Wk, bk, Wv, bv);
    attn_mma<<<dim3(16, 64), 256, ATTN_SMEM>>>(mask);
    headA_kernel<<<dim3(128, B_), 256>>>(Wo, bo);
    headB_kernel<<<dim3(64, B_), 256>>>(text, W1, b1, W2);
    headC_kernel<<<1, 32>>>(b2, out);
}

// round 9
// speedup vs baseline: 1.8827x; 1.3532x over previous
#include <cuda_runtime.h>
#include <cuda_bf16.h>

// Problem constants
#define B_ 4
#define S_ 2048
#define E_ 1024
#define H_ 16
#define D_ 64

// ---------------- scratch (bf16, [B,H,S,D]) ----------------
__device__ __nv_bfloat16 g_Qb[B_*H_*S_*D_];   // pre-scaled by 0.125*log2e
__device__ __nv_bfloat16 g_Kb[B_*H_*S_*D_];
__device__ __nv_bfloat16 g_Vb[B_*H_*S_*D_];
__device__ float g_pooled[B_*E_];
__device__ float g_o[B_*E_];
__device__ float g_nrm[B_];
__device__ float g_score[B_];

// ---------------- helpers ----------------
__device__ __forceinline__ void mma16(float* c, const unsigned* a, const unsigned* b) {
    asm("mma.sync.aligned.m16n8k16.row.col.f32.bf16.bf16.f32 "
        "{%0,%1,%2,%3}, {%4,%5,%6,%7}, {%8,%9}, {%0,%1,%2,%3};"
        : "+f"(c[0]), "+f"(c[1]), "+f"(c[2]), "+f"(c[3])
        : "r"(a[0]), "r"(a[1]), "r"(a[2]), "r"(a[3]), "r"(b[0]), "r"(b[1]));
}
__device__ __forceinline__ unsigned pack_bf2(float lo, float hi) {
    __nv_bfloat162 h = __floats2bfloat162_rn(lo, hi);
    return *reinterpret_cast<unsigned*>(&h);
}
__device__ __forceinline__ float ex2f(float x) {
    float r; asm("ex2.approx.f32 %0, %1;" : "=f"(r) : "f"(x)); return r;
}
__device__ __forceinline__ unsigned sptr(const void* p) {
    return (unsigned)__cvta_generic_to_shared(p);
}
__device__ __forceinline__ void ldsm4(unsigned* r, unsigned addr) {
    asm volatile("ldmatrix.sync.aligned.m8n8.x4.shared.b16 {%0,%1,%2,%3}, [%4];"
        : "=r"(r[0]), "=r"(r[1]), "=r"(r[2]), "=r"(r[3]) : "r"(addr));
}
__device__ __forceinline__ void ldsm4t(unsigned* r, unsigned addr) {
    asm volatile("ldmatrix.sync.aligned.m8n8.x4.trans.shared.b16 {%0,%1,%2,%3}, [%4];"
        : "=r"(r[0]), "=r"(r[1]), "=r"(r[2]), "=r"(r[3]) : "r"(addr));
}

#define QSCALE 0.18033688011112042f   // (1/sqrt(64)) * log2(e)

// =====================================================================
// zero scratch accumulators
// =====================================================================
__global__ void zero_kernel() {
    int i = blockIdx.x * blockDim.x + threadIdx.x;
    if (i < B_*E_) g_pooled[i] = 0.f;
    if (i < B_) { g_nrm[i] = 0.f; g_score[i] = 0.f; }
}

// =====================================================================
// QKV projection via bf16 mma -> bf16 scatter to [B,H,S,D]
// M=8192 N=1024 K=1024. BM=BN=128 BK=32, 256 thr (8 warps 2x4),
// warp tile 64x32, ldmatrix fragments, register prefetch.
// =====================================================================
#define QST 72   // bf16 row stride (144B = 16B-aligned, LDSM conflict-free)

__global__ __launch_bounds__(256) void qkv_mma(
    const float* __restrict__ x,
    const float* __restrict__ Wq, const float* __restrict__ bq,
    const float* __restrict__ Wk, const float* __restrict__ bk,
    const float* __restrict__ Wv, const float* __restrict__ bv)
{
    __shared__ __align__(16) __nv_bfloat16 As[128][QST];
    __shared__ __align__(16) __nv_bfloat16 Bs[128][QST];

    const int z = blockIdx.z;
    const float* __restrict__ W    = (z == 0) ? Wq : ((z == 1) ? Wk : Wv);
    const float* __restrict__ bias = (z == 0) ? bq : ((z == 1) ? bk : bv);
    __nv_bfloat16* __restrict__ out = (z == 0) ? g_Qb : ((z == 1) ? g_Kb : g_Vb);
    const float qsc = (z == 0) ? QSCALE : 1.f;

    const int tid  = threadIdx.x;
    const int lane = tid & 31, wid = tid >> 5;
    const int wm = wid >> 2, wn = wid & 3;
    const int m0 = blockIdx.y * 128, n0 = blockIdx.x * 128;
    const int g = lane >> 2, t = lane & 3;

    // ldmatrix per-lane base addresses
    const unsigned aBase = sptr(&As[wm*64 + (lane & 15)][(lane >> 4) * 8]);
    const unsigned bBase = sptr(&Bs[wn*32 + (lane & 7) + ((lane & 16) >> 1)][((lane >> 3) & 1) * 8]);

    float acc[4][4][4];
    #pragma unroll
    for (int mt = 0; mt < 4; mt++)
        #pragma unroll
        for (int nt = 0; nt < 4; nt++)
            #pragma unroll
            for (int j = 0; j < 4; j++) acc[mt][nt][j] = 0.f;

    const int lr  = tid >> 3;         // 0..31
    const int lc4 = (tid & 7) * 4;    // 0..28

    float4 va[4], vb[4];
    #pragma unroll
    for (int it = 0; it < 4; it++) {
        int rr = lr + it * 32;
        va[it] = *(const float4*)(x + (size_t)(m0 + rr) * E_ + lc4);
        vb[it] = *(const float4*)(W + (size_t)(n0 + rr) * E_ + lc4);
    }

    for (int k0 = 0; k0 < E_; k0 += 32) {
        __syncthreads();
        #pragma unroll
        for (int it = 0; it < 4; it++) {
            int rr = lr + it * 32;
            *(uint2*)&As[rr][lc4] = make_uint2(pack_bf2(va[it].x, va[it].y),
                                               pack_bf2(va[it].z, va[it].w));
            *(uint2*)&Bs[rr][lc4] = make_uint2(pack_bf2(vb[it].x, vb[it].y),
                                               pack_bf2(vb[it].z, vb[it].w));
        }
        if (k0 + 32 < E_) {
            #pragma unroll
            for (int it = 0; it < 4; it++) {
                int rr = lr + it * 32;
                va[it] = *(const float4*)(x + (size_t)(m0 + rr) * E_ + k0 + 32 + lc4);
                vb[it] = *(const float4*)(W + (size_t)(n0 + rr) * E_ + k0 + 32 + lc4);
            }
        }
        __syncthreads();

        #pragma unroll
        for (int ks = 0; ks < 2; ks++) {
            unsigned a[4][4];
            #pragma unroll
            for (int mt = 0; mt < 4; mt++)
                ldsm4(a[mt], aBase + mt * (16 * QST * 2) + ks * 32);
            #pragma unroll
            for (int p = 0; p < 2; p++) {
                unsigned bb[4];
                ldsm4(bb, bBase + p * (16 * QST * 2) + ks * 32);
                #pragma unroll
                for (int mt = 0; mt < 4; mt++) {
                    mma16(acc[mt][2*p    ], a[mt], bb);
                    mma16(acc[mt][2*p + 1], a[mt], bb + 2);
                }
            }
        }
    }

    // epilogue: bias, scale (Q only), pack bf16, scatter to [B,H,S,D]
    #pragma unroll
    for (int nt = 0; nt < 4; nt++) {
        int coln = n0 + wn * 32 + nt * 8 + 2 * t;
        int h = coln >> 6, d = coln & 63;
        float bv0 = bias[coln], bv1 = bias[coln + 1];
        #pragma unroll
        for (int mt = 0; mt < 4; mt++) {
            int gm = m0 + wm * 64 + mt * 16 + g;
            int bb = gm >> 11, s = gm & (S_ - 1);
            __nv_bfloat16* op = out + (size_t)((bb*H_ + h)*S_ + s) * D_ + d;
            *(unsigned*)op = pack_bf2((acc[mt][nt][0] + bv0) * qsc,
                                      (acc[mt][nt][1] + bv1) * qsc);
            *(unsigned*)(op + 8*D_) = pack_bf2((acc[mt][nt][2] + bv0) * qsc,
                                               (acc[mt][nt][3] + bv1) * qsc);
        }
    }
}

// =====================================================================
// Flash attention: bf16 mma + ldmatrix + ex2 softmax (log2 domain).
// 128 q rows/block (8 warps x 16), key tile 64, bf16 gmem in, prefetch.
// =====================================================================
#define AST 72
#define ATTN_SMEM ((128 + 64 + 64 + 128) * AST * 2 + 64 * 4 + 64 * 4)

__global__ __launch_bounds__(256) void attn_mma(const int* __restrict__ mask)
{
    extern __shared__ __align__(16) char smraw[];
    __nv_bfloat16* Qs = (__nv_bfloat16*)smraw;     // [128][AST]
    __nv_bfloat16* Ks = Qs + 128 * AST;            // [64][AST]  key-major
    __nv_bfloat16* Vs = Ks + 64 * AST;             // [64][AST]  key-major (trans via LDSM)
    __nv_bfloat16* Ps = Vs + 64 * AST;             // [128][AST]
    float* smf   = (float*)(Ps + 128 * AST);       // [64]
    float* spool = smf + 64;                       // [64]

    const int tid  = threadIdx.x;
    const int lane = tid & 31, wid = tid >> 5;
    const int g = lane >> 2, t = lane & 3;
    const int wrow = wid * 16;
    const int bh = blockIdx.y, b = bh >> 4;
    const int m0 = blockIdx.x * 128;

    const __nv_bfloat16* Qg = g_Qb + (size_t)(bh * S_ + m0) * D_;
    const __nv_bfloat16* Kg = g_Kb + (size_t)bh * S_ * D_;
    const __nv_bfloat16* Vg = g_Vb + (size_t)bh * S_ * D_;

    // ldmatrix per-lane base addresses
    const unsigned qA = sptr(&Qs[(wrow + (lane & 15)) * AST + (lane >> 4) * 8]);
    const unsigned pA = sptr(&Ps[(wrow + (lane & 15)) * AST + (lane >> 4) * 8]);
    const unsigned kB = sptr(&Ks[((lane & 7) + ((lane & 16) >> 1)) * AST + ((lane >> 3) & 1) * 8]);
    const unsigned vB = sptr(&Vs[(lane & 15) * AST + (lane >> 4) * 8]);

    // Q tile: straight bf16 copy (already pre-scaled)
    #pragma unroll
    for (int it = 0; it < 4; it++) {
        int lin = tid + it * 256;                // 0..1023
        int rr = lin >> 3, c8 = (lin & 7) * 8;
        *(uint4*)&Qs[rr * AST + c8] = *(const uint4*)(Qg + (size_t)rr * D_ + c8);
    }
    if (tid < 64) spool[tid] = 0.f;

    float oac[8][4];
    #pragma unroll
    for (int dt = 0; dt < 8; dt++)
        #pragma unroll
        for (int j = 0; j < 4; j++) oac[dt][j] = 0.f;
    float lsum0 = 0.f, lsum1 = 0.f;

    // prefetch regs for K/V tile + mask
    uint4 pk[2], pv[2]; int pm = 1;
    #pragma unroll
    for (int it = 0; it < 2; it++) {
        int lin = tid + it * 256;
        int rr = lin >> 3, c8 = (lin & 7) * 8;
        pk[it] = *(const uint4*)(Kg + (size_t)rr * D_ + c8);
        pv[it] = *(const uint4*)(Vg + (size_t)rr * D_ + c8);
    }
    if (tid < 64) pm = mask[b * S_ + tid];

    for (int n0t = 0; n0t < S_; n0t += 64) {
        __syncthreads();
        #pragma unroll
        for (int it = 0; it < 2; it++) {
            int lin = tid + it * 256;
            int rr = lin >> 3, c8 = (lin & 7) * 8;
            *(uint4*)&Ks[rr * AST + c8] = pk[it];
            *(uint4*)&Vs[rr * AST + c8] = pv[it];
        }
        if (tid < 64) smf[tid] = pm ? 0.f : -1e9f;
        if (n0t + 64 < S_) {
            #pragma unroll
            for (int it = 0; it < 2; it++) {
                int lin = tid + it * 256;
                int rr = lin >> 3, c8 = (lin & 7) * 8;
                pk[it] = *(const uint4*)(Kg + (size_t)(n0t + 64 + rr) * D_ + c8);
                pv[it] = *(const uint4*)(Vg + (size_t)(n0t + 64 + rr) * D_ + c8);
            }
            if (tid < 64) pm = mask[b * S_ + n0t + 64 + tid];
        }
        __syncthreads();

        // ---- S = Q K^T (log2 domain) ----
        float sc[8][4];
        #pragma unroll
        for (int nt = 0; nt < 8; nt++)
            #pragma unroll
            for (int j = 0; j < 4; j++) sc[nt][j] = 0.f;

        #pragma unroll
        for (int ks = 0; ks < 4; ks++) {
            unsigned a[4];
            ldsm4(a, qA + ks * 32);
            #pragma unroll
            for (int p = 0; p < 4; p++) {
                unsigned bb[4];
                ldsm4(bb, kB + p * (16 * AST * 2) + ks * 32);
                mma16(sc[2*p    ], a, bb);
                mma16(sc[2*p + 1], a, bb + 2);
            }
        }

        // ---- exp via MUFU ex2, accumulate lsum, pack bf16 to Ps ----
        #pragma unroll
        for (int nt = 0; nt < 8; nt++) {
            float2 mf = *(float2*)&smf[nt*8 + 2*t];
            float e0 = ex2f(sc[nt][0] + mf.x);
            float e1 = ex2f(sc[nt][1] + mf.y);
            float e2 = ex2f(sc[nt][2] + mf.x);
            float e3 = ex2f(sc[nt][3] + mf.y);
            lsum0 += e0 + e1;
            lsum1 += e2 + e3;
            *(unsigned*)&Ps[(wrow + g    ) * AST + nt*8 + 2*t] = pack_bf2(e0, e1);
            *(unsigned*)&Ps[(wrow + g + 8) * AST + nt*8 + 2*t] = pack_bf2(e2, e3);
        }
        __syncwarp();

        // ---- O += P V  (V B-fragments via ldmatrix.trans on k-major tile) ----
        #pragma unroll
        for (int ks = 0; ks < 4; ks++) {
            unsigned a[4];
            ldsm4(a, pA + ks * 32);
            #pragma unroll
            for (int p = 0; p < 4; p++) {
                unsigned bb[4];
                ldsm4t(bb, vB + ks * (16 * AST * 2) + p * 32);
                mma16(oac[2*p    ], a, bb);
                mma16(oac[2*p + 1], a, bb + 2);
            }
        }
    }

    // ---- epilogue: normalize rows, block-local pooled reduction ----
    lsum0 += __shfl_xor_sync(0xffffffffu, lsum0, 1);
    lsum0 += __shfl_xor_sync(0xffffffffu, lsum0, 2);
    lsum1 += __shfl_xor_sync(0xffffffffu, lsum1, 1);
    lsum1 += __shfl_xor_sync(0xffffffffu, lsum1, 2);
    float inv0 = 1.f / lsum0, inv1 = 1.f / lsum1;

    #pragma unroll
    for (int dt = 0; dt < 8; dt++) {
        float p0 = oac[dt][0] * inv0 + oac[dt][2] * inv1;
        float p1 = oac[dt][1] * inv0 + oac[dt][3] * inv1;
        p0 += __shfl_xor_sync(0xffffffffu, p0, 4);
        p0 += __shfl_xor_sync(0xffffffffu, p0, 8);
        p0 += __shfl_xor_sync(0xffffffffu, p0, 16);
        p1 += __shfl_xor_sync(0xffffffffu, p1, 4);
        p1 += __shfl_xor_sync(0xffffffffu, p1, 8);
        p1 += __shfl_xor_sync(0xffffffffu, p1, 16);
        if (lane < 4) {
            atomicAdd(&spool[dt*8 + 2*t    ], p0);
            atomicAdd(&spool[dt*8 + 2*t + 1], p1);
        }
    }
    __syncthreads();
    if (tid < 64) {
        const int h = bh & 15;
        atomicAdd(&g_pooled[b*E_ + h*64 + tid], spool[tid]);
    }
}

// =====================================================================
// head A: o = (pooled/S) @ Wo^T + bo ; accumulate squared norm
// =====================================================================
__global__ __launch_bounds__(256) void headA_kernel(
    const float* __restrict__ Wo, const float* __restrict__ bo)
{
    const int b = blockIdx.y;
    const int n = blockIdx.x * 8 + (threadIdx.x >> 5);
    const int lane = threadIdx.x & 31;
    const float* pr = g_pooled + b * E_;
    const float* wr = Wo + (size_t)n * E_;
    float acc = 0.f;
    #pragma unroll
    for (int i = 0; i < 8; i++) {
        int k = i * 128 + lane * 4;
        float4 w = *(const float4*)(wr + k);
        float4 p = *(const float4*)(pr + k);
        acc += p.x*w.x + p.y*w.y + p.z*w.z + p.w*w.w;
    }
    #pragma unroll
    for (int off = 16; off > 0; off >>= 1)
        acc += __shfl_xor_sync(0xffffffffu, acc, off);
    if (lane == 0) {
        float o = acc * (1.0f / S_) + bo[n];
        g_o[b * E_ + n] = o;
        atomicAdd(&g_nrm[b], o * o);
    }
}

// =====================================================================
// head B: u = o/||o|| - text ; h = relu(u @ W1^T + b1) ; score += h*W2
// =====================================================================
__global__ __launch_bounds__(256) void headB_kernel(
    const float* __restrict__ text,
    const float* __restrict__ W1, const float* __restrict__ b1,
    const float* __restrict__ W2)
{
    const int b = blockIdx.y;
    const int rr = blockIdx.x * 8 + (threadIdx.x >> 5);
    const int lane = threadIdx.x & 31;
    const float rinv = rsqrtf(g_nrm[b]);
    const float* orow = g_o + b * E_;
    const float* trow = text + b * E_;
    const float* wr = W1 + (size_t)rr * E_;
    float acc = 0.f;
    #pragma unroll
    for (int i = 0; i < 8; i++) {
        int k = i * 128 + lane * 4;
        float4 w = *(const float4*)(wr + k);
        float4 o = *(const float4*)(orow + k);
        float4 tt = *(const float4*)(trow + k);
        acc += (o.x*rinv - tt.x)*w.x + (o.y*rinv - tt.y)*w.y
             + (o.z*rinv - tt.z)*w.z + (o.w*rinv - tt.w)*w.w;
    }
    #pragma unroll
    for (int off = 16; off > 0; off >>= 1)
        acc += __shfl_xor_sync(0xffffffffu, acc, off);
    if (lane == 0) {
        float hv = fmaxf(acc + b1[rr], 0.f);
        atomicAdd(&g_score[b], hv * W2[rr]);
    }
}

__global__ void headC_kernel(const float* __restrict__ b2, float* __restrict__ out)
{
    int i = threadIdx.x;
    if (i < B_) out[i] = tanhf(g_score[i] + b2[0]);
}

// =====================================================================
// Launch
// =====================================================================
extern "C" void kernel_launch(void* const* d_in, const int* in_sizes, int n_in,
                              void* d_out, int out_size)
{
    (void)in_sizes; (void)n_in; (void)out_size;
    const float* x    = (const float*)d_in[0];
    const int*   mask = (const int*)  d_in[1];
    const float* text = (const float*)d_in[2];
    const float* Wq = (const float*)d_in[3];
    const float* bq = (const float*)d_in[4];
    const float* Wk = (const float*)d_in[5];
    const float* bk = (const float*)d_in[6];
    const float* Wv = (const float*)d_in[7];
    const float* bv = (const float*)d_in[8];
    const float* Wo = (const float*)d_in[9];
    const float* bo = (const float*)d_in[10];
    const float* W1 = (const float*)d_in[11];
    const float* b1 = (const float*)d_in[12];
    const float* W2 = (const float*)d_in[13];
    const float* b2 = (const float*)d_in[14];
    float* out = (float*)d_out;

    cudaFuncSetAttribute(attn_mma, cudaFuncAttributeMaxDynamicSharedMemorySize, ATTN_SMEM);

    zero_kernel<<<16, 256>>>();
    qkv_mma<<<dim3(8, 64, 3), 256>>>(x, Wq, bq, Wk, bk, Wv, bv);
    attn_mma<<<dim3(16, 64), 256, ATTN_SMEM>>>(mask);
    headA_kernel<<<dim3(128, B_), 256>>>(Wo, bo);
    headB_kernel<<<dim3(64, B_), 256>>>(text, W1, b1, W2);
    headC_kernel<<<1, 32>>>(b2, out);
}

// round 10
// speedup vs baseline: 2.0241x; 1.0751x over previous
#include <cuda_runtime.h>
#include <cuda_bf16.h>

// Problem constants
#define B_ 4
#define S_ 2048
#define E_ 1024
#define H_ 16
#define D_ 64

// ---------------- scratch (bf16, [B,H,S,D]) ----------------
__device__ __nv_bfloat16 g_Qb[B_*H_*S_*D_];   // pre-scaled by 0.125*log2e
__device__ __nv_bfloat16 g_Kb[B_*H_*S_*D_];
__device__ __nv_bfloat16 g_Vb[B_*H_*S_*D_];
__device__ float g_pooled[B_*E_];
__device__ float g_o[B_*E_];
__device__ float g_nrm[B_];
__device__ float g_score[B_];

// ---------------- helpers ----------------
__device__ __forceinline__ void mma16(float* c, const unsigned* a, const unsigned* b) {
    asm("mma.sync.aligned.m16n8k16.row.col.f32.bf16.bf16.f32 "
        "{%0,%1,%2,%3}, {%4,%5,%6,%7}, {%8,%9}, {%0,%1,%2,%3};"
        : "+f"(c[0]), "+f"(c[1]), "+f"(c[2]), "+f"(c[3])
        : "r"(a[0]), "r"(a[1]), "r"(a[2]), "r"(a[3]), "r"(b[0]), "r"(b[1]));
}
__device__ __forceinline__ unsigned pack_bf2(float lo, float hi) {
    __nv_bfloat162 h = __floats2bfloat162_rn(lo, hi);
    return *reinterpret_cast<unsigned*>(&h);
}
__device__ __forceinline__ float ex2f(float x) {
    float r; asm("ex2.approx.f32 %0, %1;" : "=f"(r) : "f"(x)); return r;
}
__device__ __forceinline__ unsigned sptr(const void* p) {
    return (unsigned)__cvta_generic_to_shared(p);
}
__device__ __forceinline__ void ldsm4(unsigned* r, unsigned addr) {
    asm volatile("ldmatrix.sync.aligned.m8n8.x4.shared.b16 {%0,%1,%2,%3}, [%4];"
        : "=r"(r[0]), "=r"(r[1]), "=r"(r[2]), "=r"(r[3]) : "r"(addr));
}
__device__ __forceinline__ void ldsm4t(unsigned* r, unsigned addr) {
    asm volatile("ldmatrix.sync.aligned.m8n8.x4.trans.shared.b16 {%0,%1,%2,%3}, [%4];"
        : "=r"(r[0]), "=r"(r[1]), "=r"(r[2]), "=r"(r[3]) : "r"(addr));
}

#define QSCALE 0.18033688011112042f   // (1/sqrt(64)) * log2(e)

// =====================================================================
// zero scratch accumulators
// =====================================================================
__global__ void zero_kernel() {
    int i = blockIdx.x * blockDim.x + threadIdx.x;
    if (i < B_*E_) g_pooled[i] = 0.f;
    if (i < B_) { g_nrm[i] = 0.f; g_score[i] = 0.f; }
}

// =====================================================================
// QKV projection via bf16 mma -> bf16 scatter to [B,H,S,D]
// BM=BN=128 BK=32, 256 thr (8 warps 2x4), warp tile 64x32.
// Double-buffered smem (stride 40), one sync per k-step, 2-deep LDG pipe.
// =====================================================================
#define QST 40   // 32 + 8 pad; LDSM phases hit distinct bank-quads ((5r)%8)

__global__ __launch_bounds__(256) void qkv_mma(
    const float* __restrict__ x,
    const float* __restrict__ Wq, const float* __restrict__ bq,
    const float* __restrict__ Wk, const float* __restrict__ bk,
    const float* __restrict__ Wv, const float* __restrict__ bv)
{
    __shared__ __align__(16) __nv_bfloat16 As[2][128][QST];
    __shared__ __align__(16) __nv_bfloat16 Bs[2][128][QST];

    const int z = blockIdx.z;
    const float* __restrict__ W    = (z == 0) ? Wq : ((z == 1) ? Wk : Wv);
    const float* __restrict__ bias = (z == 0) ? bq : ((z == 1) ? bk : bv);
    __nv_bfloat16* __restrict__ out = (z == 0) ? g_Qb : ((z == 1) ? g_Kb : g_Vb);
    const float qsc = (z == 0) ? QSCALE : 1.f;

    const int tid  = threadIdx.x;
    const int lane = tid & 31, wid = tid >> 5;
    const int wm = wid >> 2, wn = wid & 3;
    const int m0 = blockIdx.y * 128, n0 = blockIdx.x * 128;
    const int g = lane >> 2, t = lane & 3;

    const unsigned BUFA = (unsigned)(128 * QST * 2);   // bytes per buffer
    const unsigned aBase = sptr(&As[0][wm*64 + (lane & 15)][(lane >> 4) * 8]);
    const unsigned bBase = sptr(&Bs[0][wn*32 + (lane & 7) + ((lane & 16) >> 1)][((lane >> 3) & 1) * 8]);

    float acc[4][4][4];
    #pragma unroll
    for (int mt = 0; mt < 4; mt++)
        #pragma unroll
        for (int nt = 0; nt < 4; nt++)
            #pragma unroll
            for (int j = 0; j < 4; j++) acc[mt][nt][j] = 0.f;

    const int lr  = tid >> 3;         // 0..31
    const int lc4 = (tid & 7) * 4;    // 0..28

    float4 va[4], vb[4];
    // prologue: tile 0 -> buf0, stage tile 1 in regs
    #pragma unroll
    for (int it = 0; it < 4; it++) {
        int rr = lr + it * 32;
        va[it] = *(const float4*)(x + (size_t)(m0 + rr) * E_ + lc4);
        vb[it] = *(const float4*)(W + (size_t)(n0 + rr) * E_ + lc4);
    }
    #pragma unroll
    for (int it = 0; it < 4; it++) {
        int rr = lr + it * 32;
        *(uint2*)&As[0][rr][lc4] = make_uint2(pack_bf2(va[it].x, va[it].y),
                                              pack_bf2(va[it].z, va[it].w));
        *(uint2*)&Bs[0][rr][lc4] = make_uint2(pack_bf2(vb[it].x, vb[it].y),
                                              pack_bf2(vb[it].z, vb[it].w));
    }
    #pragma unroll
    for (int it = 0; it < 4; it++) {
        int rr = lr + it * 32;
        va[it] = *(const float4*)(x + (size_t)(m0 + rr) * E_ + 32 + lc4);
        vb[it] = *(const float4*)(W + (size_t)(n0 + rr) * E_ + 32 + lc4);
    }
    __syncthreads();

    for (int i = 0; i < 32; i++) {
        const unsigned cb = (i & 1) * BUFA;
        const int nxt = (i + 1) & 1;
        if (i + 1 < 32) {
            #pragma unroll
            for (int it = 0; it < 4; it++) {
                int rr = lr + it * 32;
                *(uint2*)&As[nxt][rr][lc4] = make_uint2(pack_bf2(va[it].x, va[it].y),
                                                        pack_bf2(va[it].z, va[it].w));
                *(uint2*)&Bs[nxt][rr][lc4] = make_uint2(pack_bf2(vb[it].x, vb[it].y),
                                                        pack_bf2(vb[it].z, vb[it].w));
            }
        }
        if (i + 2 < 32) {
            int k0 = (i + 2) * 32;
            #pragma unroll
            for (int it = 0; it < 4; it++) {
                int rr = lr + it * 32;
                va[it] = *(const float4*)(x + (size_t)(m0 + rr) * E_ + k0 + lc4);
                vb[it] = *(const float4*)(W + (size_t)(n0 + rr) * E_ + k0 + lc4);
            }
        }

        #pragma unroll
        for (int ks = 0; ks < 2; ks++) {
            unsigned a[4][4];
            #pragma unroll
            for (int mt = 0; mt < 4; mt++)
                ldsm4(a[mt], aBase + cb + mt * (16 * QST * 2) + ks * 32);
            #pragma unroll
            for (int p = 0; p < 2; p++) {
                unsigned bb[4];
                ldsm4(bb, bBase + cb + p * (16 * QST * 2) + ks * 32);
                #pragma unroll
                for (int mt = 0; mt < 4; mt++) {
                    mma16(acc[mt][2*p    ], a[mt], bb);
                    mma16(acc[mt][2*p + 1], a[mt], bb + 2);
                }
            }
        }
        __syncthreads();
    }

    // epilogue: bias, scale (Q only), pack bf16, scatter to [B,H,S,D]
    #pragma unroll
    for (int nt = 0; nt < 4; nt++) {
        int coln = n0 + wn * 32 + nt * 8 + 2 * t;
        int h = coln >> 6, d = coln & 63;
        float bv0 = bias[coln], bv1 = bias[coln + 1];
        #pragma unroll
        for (int mt = 0; mt < 4; mt++) {
            int gm = m0 + wm * 64 + mt * 16 + g;
            int bb = gm >> 11, s = gm & (S_ - 1);
            __nv_bfloat16* op = out + (size_t)((bb*H_ + h)*S_ + s) * D_ + d;
            *(unsigned*)op = pack_bf2((acc[mt][nt][0] + bv0) * qsc,
                                      (acc[mt][nt][1] + bv1) * qsc);
            *(unsigned*)(op + 8*D_) = pack_bf2((acc[mt][nt][2] + bv0) * qsc,
                                               (acc[mt][nt][3] + bv1) * qsc);
        }
    }
}

// =====================================================================
// Flash attention: bf16 mma + ldmatrix + ex2 softmax (log2 domain).
// 128 q rows/block (8 warps x 16), key tile 64. Double-buffered K/V
// (1 sync/tile), P stays in registers (QK accum == PV A-fragment layout).
// =====================================================================
#define AST 72
// Qs | K0 V0 K1 V1 | smf[2][64] | spool[64]
#define Q_BYTES   (128 * AST * 2)
#define KV_BYTES  (64 * AST * 2)
#define ATTN_SMEM (Q_BYTES + 4 * KV_BYTES + 2 * 64 * 4 + 64 * 4)

__global__ __launch_bounds__(256, 2) void attn_mma(const int* __restrict__ mask)
{
    extern __shared__ __align__(16) char smraw[];
    __nv_bfloat16* Qs = (__nv_bfloat16*)smraw;          // [128][AST]
    __nv_bfloat16* Ks = Qs + 128 * AST;                 // buf0: K,V ; buf1: K,V
    __nv_bfloat16* Vs = Ks + 64 * AST;
    float* smf   = (float*)(smraw + Q_BYTES + 4 * KV_BYTES);  // [2][64]
    float* spool = smf + 128;                                 // [64]

    const int tid  = threadIdx.x;
    const int lane = tid & 31, wid = tid >> 5;
    const int g = lane >> 2, t = lane & 3;
    const int wrow = wid * 16;
    const int bh = blockIdx.y, b = bh >> 4;
    const int m0 = blockIdx.x * 128;
    const unsigned KVB = 2 * KV_BYTES;   // byte stride between buffers

    const __nv_bfloat16* Qg = g_Qb + (size_t)(bh * S_ + m0) * D_;
    const __nv_bfloat16* Kg = g_Kb + (size_t)bh * S_ * D_;
    const __nv_bfloat16* Vg = g_Vb + (size_t)bh * S_ * D_;

    const unsigned qA = sptr(&Qs[(wrow + (lane & 15)) * AST + (lane >> 4) * 8]);
    const unsigned kB = sptr(&Ks[((lane & 7) + ((lane & 16) >> 1)) * AST + ((lane >> 3) & 1) * 8]);
    const unsigned vB = sptr(&Vs[(lane & 15) * AST + (lane >> 4) * 8]);

    // Q tile: straight bf16 copy (already pre-scaled)
    #pragma unroll
    for (int it = 0; it < 4; it++) {
        int lin = tid + it * 256;
        int rr = lin >> 3, c8 = (lin & 7) * 8;
        *(uint4*)&Qs[rr * AST + c8] = *(const uint4*)(Qg + (size_t)rr * D_ + c8);
    }
    if (tid < 64) spool[tid] = 0.f;

    float oac[8][4];
    #pragma unroll
    for (int dt = 0; dt < 8; dt++)
        #pragma unroll
        for (int j = 0; j < 4; j++) oac[dt][j] = 0.f;
    float lsum0 = 0.f, lsum1 = 0.f;

    const int rr0 = tid >> 3, c8_ = (tid & 7) * 8;     // tile-load coords
    const int rr1 = rr0 + 32;

    // prologue: tile0 -> buf0, stage tile1 in regs
    uint4 pk[2], pv[2]; int pm = 1;
    pk[0] = *(const uint4*)(Kg + (size_t)rr0 * D_ + c8_);
    pk[1] = *(const uint4*)(Kg + (size_t)rr1 * D_ + c8_);
    pv[0] = *(const uint4*)(Vg + (size_t)rr0 * D_ + c8_);
    pv[1] = *(const uint4*)(Vg + (size_t)rr1 * D_ + c8_);
    *(uint4*)&Ks[rr0 * AST + c8_] = pk[0];
    *(uint4*)&Ks[rr1 * AST + c8_] = pk[1];
    *(uint4*)&Vs[rr0 * AST + c8_] = pv[0];
    *(uint4*)&Vs[rr1 * AST + c8_] = pv[1];
    if (tid < 64) smf[tid] = mask[b * S_ + tid] ? 0.f : -1e9f;
    pk[0] = *(const uint4*)(Kg + (size_t)(64 + rr0) * D_ + c8_);
    pk[1] = *(const uint4*)(Kg + (size_t)(64 + rr1) * D_ + c8_);
    pv[0] = *(const uint4*)(Vg + (size_t)(64 + rr0) * D_ + c8_);
    pv[1] = *(const uint4*)(Vg + (size_t)(64 + rr1) * D_ + c8_);
    if (tid < 64) pm = mask[b * S_ + 64 + tid];
    __syncthreads();

    for (int i = 0; i < 32; i++) {
        const unsigned cb = (i & 1) * KVB;
        const int nxt = (i + 1) & 1;
        if (i + 1 < 32) {
            __nv_bfloat16* Kn = Ks + nxt * (KVB / 2);   // elements
            __nv_bfloat16* Vn = Vs + nxt * (KVB / 2);
            *(uint4*)&Kn[rr0 * AST + c8_] = pk[0];
            *(uint4*)&Kn[rr1 * AST + c8_] = pk[1];
            *(uint4*)&Vn[rr0 * AST + c8_] = pv[0];
            *(uint4*)&Vn[rr1 * AST + c8_] = pv[1];
            if (tid < 64) smf[nxt * 64 + tid] = pm ? 0.f : -1e9f;
        }
        if (i + 2 < 32) {
            size_t base = (size_t)((i + 2) * 64);
            pk[0] = *(const uint4*)(Kg + (base + rr0) * D_ + c8_);
            pk[1] = *(const uint4*)(Kg + (base + rr1) * D_ + c8_);
            pv[0] = *(const uint4*)(Vg + (base + rr0) * D_ + c8_);
            pv[1] = *(const uint4*)(Vg + (base + rr1) * D_ + c8_);
            if (tid < 64) pm = mask[b * S_ + (i + 2) * 64 + tid];
        }

        // ---- S = Q K^T (log2 domain) ----
        float sc[8][4];
        #pragma unroll
        for (int nt = 0; nt < 8; nt++)
            #pragma unroll
            for (int j = 0; j < 4; j++) sc[nt][j] = 0.f;

        #pragma unroll
        for (int ks = 0; ks < 4; ks++) {
            unsigned a[4];
            ldsm4(a, qA + ks * 32);
            #pragma unroll
            for (int p = 0; p < 4; p++) {
                unsigned bb[4];
                ldsm4(bb, kB + cb + p * (16 * AST * 2) + ks * 32);
                mma16(sc[2*p    ], a, bb);
                mma16(sc[2*p + 1], a, bb + 2);
            }
        }

        // ---- exp via MUFU ex2, lsum, pack directly into PV A-fragments ----
        unsigned pfrag[16];
        const float* mfb = smf + (i & 1) * 64;
        #pragma unroll
        for (int nt = 0; nt < 8; nt++) {
            float2 mf = *(const float2*)&mfb[nt*8 + 2*t];
            float e0 = ex2f(sc[nt][0] + mf.x);
            float e1 = ex2f(sc[nt][1] + mf.y);
            float e2 = ex2f(sc[nt][2] + mf.x);
            float e3 = ex2f(sc[nt][3] + mf.y);
            lsum0 += e0 + e1;
            lsum1 += e2 + e3;
            pfrag[2*nt    ] = pack_bf2(e0, e1);   // (row g,   cols nt*8+2t..)
            pfrag[2*nt + 1] = pack_bf2(e2, e3);   // (row g+8, cols nt*8+2t..)
        }

        // ---- O += P V  (A-fragments already in registers) ----
        #pragma unroll
        for (int ks = 0; ks < 4; ks++) {
            #pragma unroll
            for (int p = 0; p < 4; p++) {
                unsigned bb[4];
                ldsm4t(bb, vB + cb + ks * (16 * AST * 2) + p * 32);
                mma16(oac[2*p    ], &pfrag[4*ks], bb);
                mma16(oac[2*p + 1], &pfrag[4*ks], bb + 2);
            }
        }
        __syncthreads();
    }

    // ---- epilogue: normalize rows, block-local pooled reduction ----
    lsum0 += __shfl_xor_sync(0xffffffffu, lsum0, 1);
    lsum0 += __shfl_xor_sync(0xffffffffu, lsum0, 2);
    lsum1 += __shfl_xor_sync(0xffffffffu, lsum1, 1);
    lsum1 += __shfl_xor_sync(0xffffffffu, lsum1, 2);
    float inv0 = 1.f / lsum0, inv1 = 1.f / lsum1;

    #pragma unroll
    for (int dt = 0; dt < 8; dt++) {
        float p0 = oac[dt][0] * inv0 + oac[dt][2] * inv1;
        float p1 = oac[dt][1] * inv0 + oac[dt][3] * inv1;
        p0 += __shfl_xor_sync(0xffffffffu, p0, 4);
        p0 += __shfl_xor_sync(0xffffffffu, p0, 8);
        p0 += __shfl_xor_sync(0xffffffffu, p0, 16);
        p1 += __shfl_xor_sync(0xffffffffu, p1, 4);
        p1 += __shfl_xor_sync(0xffffffffu, p1, 8);
        p1 += __shfl_xor_sync(0xffffffffu, p1, 16);
        if (lane < 4) {
            atomicAdd(&spool[dt*8 + 2*t    ], p0);
            atomicAdd(&spool[dt*8 + 2*t + 1], p1);
        }
    }
    __syncthreads();
    if (tid < 64) {
        const int h = bh & 15;
        atomicAdd(&g_pooled[b*E_ + h*64 + tid], spool[tid]);
    }
}

// =====================================================================
// head A: o = (pooled/S) @ Wo^T + bo ; accumulate squared norm
// =====================================================================
__global__ __launch_bounds__(256) void headA_kernel(
    const float* __restrict__ Wo, const float* __restrict__ bo)
{
    const int b = blockIdx.y;
    const int n = blockIdx.x * 8 + (threadIdx.x >> 5);
    const int lane = threadIdx.x & 31;
    const float* pr = g_pooled + b * E_;
    const float* wr = Wo + (size_t)n * E_;
    float acc = 0.f;
    #pragma unroll
    for (int i = 0; i < 8; i++) {
        int k = i * 128 + lane * 4;
        float4 w = *(const float4*)(wr + k);
        float4 p = *(const float4*)(pr + k);
        acc += p.x*w.x + p.y*w.y + p.z*w.z + p.w*w.w;
    }
    #pragma unroll
    for (int off = 16; off > 0; off >>= 1)
        acc += __shfl_xor_sync(0xffffffffu, acc, off);
    if (lane == 0) {
        float o = acc * (1.0f / S_) + bo[n];
        g_o[b * E_ + n] = o;
        atomicAdd(&g_nrm[b], o * o);
    }
}

// =====================================================================
// head B: u = o/||o|| - text ; h = relu(u @ W1^T + b1) ; score += h*W2
// =====================================================================
__global__ __launch_bounds__(256) void headB_kernel(
    const float* __restrict__ text,
    const float* __restrict__ W1, const float* __restrict__ b1,
    const float* __restrict__ W2)
{
    const int b = blockIdx.y;
    const int rr = blockIdx.x * 8 + (threadIdx.x >> 5);
    const int lane = threadIdx.x & 31;
    const float rinv = rsqrtf(g_nrm[b]);
    const float* orow = g_o + b * E_;
    const float* trow = text + b * E_;
    const float* wr = W1 + (size_t)rr * E_;
    float acc = 0.f;
    #pragma unroll
    for (int i = 0; i < 8; i++) {
        int k = i * 128 + lane * 4;
        float4 w = *(const float4*)(wr + k);
        float4 o = *(const float4*)(orow + k);
        float4 tt = *(const float4*)(trow + k);
        acc += (o.x*rinv - tt.x)*w.x + (o.y*rinv - tt.y)*w.y
             + (o.z*rinv - tt.z)*w.z + (o.w*rinv - tt.w)*w.w;
    }
    #pragma unroll
    for (int off = 16; off > 0; off >>= 1)
        acc += __shfl_xor_sync(0xffffffffu, acc, off);
    if (lane == 0) {
        float hv = fmaxf(acc + b1[rr], 0.f);
        atomicAdd(&g_score[b], hv * W2[rr]);
    }
}

__global__ void headC_kernel(const float* __restrict__ b2, float* __restrict__ out)
{
    int i = threadIdx.x;
    if (i < B_) out[i] = tanhf(g_score[i] + b2[0]);
}

// =====================================================================
// Launch
// =====================================================================
extern "C" void kernel_launch(void* const* d_in, const int* in_sizes, int n_in,
                              void* d_out, int out_size)
{
    (void)in_sizes; (void)n_in; (void)out_size;
    const float* x    = (const float*)d_in[0];
    const int*   mask = (const int*)  d_in[1];
    const float* text = (const float*)d_in[2];
    const float* Wq = (const float*)d_in[3];
    const float* bq = (const float*)d_in[4];
    const float* Wk = (const float*)d_in[5];
    const float* bk = (const float*)d_in[6];
    const float* Wv = (const float*)d_in[7];
    const float* bv = (const float*)d_in[8];
    const float* Wo = (const float*)d_in[9];
    const float* bo = (const float*)d_in[10];
    const float* W1 = (const float*)d_in[11];
    const float* b1 = (const float*)d_in[12];
    const float* W2 = (const float*)d_in[13];
    const float* b2 = (const float*)d_in[14];
    float* out = (float*)d_out;

    cudaFuncSetAttribute(attn_mma, cudaFuncAttributeMaxDynamicSharedMemorySize, ATTN_SMEM);

    zero_kernel<<<16, 256>>>();
    qkv_mma<<<dim3(8, 64, 3), 256>>>(x, Wq, bq, Wk, bk, Wv, bv);
    attn_mma<<<dim3(16, 64), 256, ATTN_SMEM>>>(mask);
    headA_kernel<<<dim3(128, B_), 256>>>(Wo, bo);
    headB_kernel<<<dim3(64, B_), 256>>>(text, W1, b1, W2);
    headC_kernel<<<1, 32>>>(b2, out);
}

// round 11
// speedup vs baseline: 2.4614x; 1.2160x over previous
#include <cuda_runtime.h>
#include <cuda_bf16.h>

// Problem constants
#define B_ 4
#define S_ 2048
#define E_ 1024
#define H_ 16
#define D_ 64
#define XN (B_*S_*E_)     // 8388608
#define WN (E_*E_)        // 1048576

// ---------------- scratch ----------------
__device__ __nv_bfloat16 g_xb[XN];            // bf16 copy of x
__device__ __nv_bfloat16 g_Wb[3*WN];          // bf16 Wq|Wk|Wv
__device__ __nv_bfloat16 g_Qb[B_*H_*S_*D_];   // pre-scaled by 0.125*log2e
__device__ __nv_bfloat16 g_Kb[B_*H_*S_*D_];
__device__ __nv_bfloat16 g_Vb[B_*H_*S_*D_];
__device__ float g_pooled[B_*E_];
__device__ float g_o[B_*E_];
__device__ float g_nrm[B_];
__device__ float g_score[B_];

// ---------------- helpers ----------------
__device__ __forceinline__ void mma16(float* c, const unsigned* a, const unsigned* b) {
    asm("mma.sync.aligned.m16n8k16.row.col.f32.bf16.bf16.f32 "
        "{%0,%1,%2,%3}, {%4,%5,%6,%7}, {%8,%9}, {%0,%1,%2,%3};"
        : "+f"(c[0]), "+f"(c[1]), "+f"(c[2]), "+f"(c[3])
        : "r"(a[0]), "r"(a[1]), "r"(a[2]), "r"(a[3]), "r"(b[0]), "r"(b[1]));
}
__device__ __forceinline__ unsigned pack_bf2(float lo, float hi) {
    __nv_bfloat162 h = __floats2bfloat162_rn(lo, hi);
    return *reinterpret_cast<unsigned*>(&h);
}
__device__ __forceinline__ float ex2f(float x) {
    float r; asm("ex2.approx.f32 %0, %1;" : "=f"(r) : "f"(x)); return r;
}
__device__ __forceinline__ unsigned sptr(const void* p) {
    return (unsigned)__cvta_generic_to_shared(p);
}
__device__ __forceinline__ void ldsm4(unsigned* r, unsigned addr) {
    asm volatile("ldmatrix.sync.aligned.m8n8.x4.shared.b16 {%0,%1,%2,%3}, [%4];"
        : "=r"(r[0]), "=r"(r[1]), "=r"(r[2]), "=r"(r[3]) : "r"(addr));
}
__device__ __forceinline__ void ldsm4t(unsigned* r, unsigned addr) {
    asm volatile("ldmatrix.sync.aligned.m8n8.x4.trans.shared.b16 {%0,%1,%2,%3}, [%4];"
        : "=r"(r[0]), "=r"(r[1]), "=r"(r[2]), "=r"(r[3]) : "r"(addr));
}
__device__ __forceinline__ void cpa16(unsigned s, const void* g) {
    asm volatile("cp.async.cg.shared.global [%0], [%1], 16;" :: "r"(s), "l"(g));
}
__device__ __forceinline__ void cpcommit() { asm volatile("cp.async.commit_group;"); }
template<int N> __device__ __forceinline__ void cpwait() {
    asm volatile("cp.async.wait_group %0;" :: "n"(N));
}

#define QSCALE 0.18033688011112042f   // (1/sqrt(64)) * log2(e)

// =====================================================================
// zero scratch accumulators
// =====================================================================
__global__ void zero_kernel() {
    int i = blockIdx.x * blockDim.x + threadIdx.x;
    if (i < B_*E_) g_pooled[i] = 0.f;
    if (i < B_) { g_nrm[i] = 0.f; g_score[i] = 0.f; }
}

// =====================================================================
// one-shot fp32 -> bf16 conversion of x and Wq/Wk/Wv
// =====================================================================
__global__ __launch_bounds__(256) void cvt_kernel(
    const float* __restrict__ x,
    const float* __restrict__ Wq, const float* __restrict__ Wk,
    const float* __restrict__ Wv)
{
    const int i = blockIdx.x * blockDim.x + threadIdx.x;   // float4 index
    const int total = (XN + 3*WN) / 4;
    if (i >= total) return;
    int v = i * 4;
    const float* src;
    __nv_bfloat16* dst;
    if (v < XN) {
        src = x + v; dst = g_xb + v;
    } else {
        int w = v - XN;
        int z = w / WN, r = w - z * WN;
        src = (z == 0 ? Wq : (z == 1 ? Wk : Wv)) + r;
        dst = g_Wb + z * WN + r;
    }
    float4 f = *(const float4*)src;
    *(uint2*)dst = make_uint2(pack_bf2(f.x, f.y), pack_bf2(f.z, f.w));
}

// =====================================================================
// QKV projection via bf16 mma on bf16 inputs -> bf16 scatter [B,H,S,D]
// BM=BN=128 BK=64, 256 thr (8 warps 2x4), warp tile 64x32.
// cp.async 3-stage pipeline, one sync per k-iter (16 iters).
// =====================================================================
#define QKST 72
#define QKV_STG (128 * QKST)                 // elems per stage per array
#define QKV_SMEM (3 * 2 * QKV_STG * 2)       // 110592 B

__global__ __launch_bounds__(256) void qkv_mma(
    const float* __restrict__ bq, const float* __restrict__ bk,
    const float* __restrict__ bv)
{
    extern __shared__ __align__(16) char qsm[];
    __nv_bfloat16* As = (__nv_bfloat16*)qsm;          // [3][128][QKST]
    __nv_bfloat16* Bs = As + 3 * QKV_STG;

    const int z = blockIdx.z;
    const float* __restrict__ bias = (z == 0) ? bq : ((z == 1) ? bk : bv);
    __nv_bfloat16* __restrict__ out = (z == 0) ? g_Qb : ((z == 1) ? g_Kb : g_Vb);
    const float qsc = (z == 0) ? QSCALE : 1.f;

    const int tid  = threadIdx.x;
    const int lane = tid & 31, wid = tid >> 5;
    const int wm = wid >> 2, wn = wid & 3;
    const int m0 = blockIdx.y * 128, n0 = blockIdx.x * 128;
    const int g = lane >> 2, t = lane & 3;

    const __nv_bfloat16* Xg = g_xb + (size_t)m0 * E_;
    const __nv_bfloat16* Wg = g_Wb + (size_t)z * WN + (size_t)n0 * E_;

    // per-thread copy coords: 4 x 16B per array per tile
    const int crow = tid >> 3;            // 0..31 (+32*it)
    const int ccol = (tid & 7) * 8;       // bf16 elems

    const unsigned aS0 = sptr(As) + (unsigned)(crow * QKST + ccol) * 2;
    const unsigned bS0 = sptr(Bs) + (unsigned)(crow * QKST + ccol) * 2;

    // issue one k-tile into stage s
    auto issue = [&](int kt, int s) {
        unsigned so = (unsigned)(s * QKV_STG * 2);
        const __nv_bfloat16* xa = Xg + (size_t)crow * E_ + kt * 64 + ccol;
        const __nv_bfloat16* wb = Wg + (size_t)crow * E_ + kt * 64 + ccol;
        #pragma unroll
        for (int it = 0; it < 4; it++) {
            cpa16(aS0 + so + it * (32 * QKST * 2), xa + (size_t)(it * 32) * E_);
            cpa16(bS0 + so + it * (32 * QKST * 2), wb + (size_t)(it * 32) * E_);
        }
        cpcommit();
    };

    // ldmatrix per-lane bases (stage 0)
    const unsigned aBase = sptr(As) +
        (unsigned)((wm*64 + (lane & 15)) * QKST + (lane >> 4) * 8) * 2;
    const unsigned bBase = sptr(Bs) +
        (unsigned)((wn*32 + (lane & 7) + ((lane & 16) >> 1)) * QKST + ((lane >> 3) & 1) * 8) * 2;

    float acc[4][4][4];
    #pragma unroll
    for (int mt = 0; mt < 4; mt++)
        #pragma unroll
        for (int nt = 0; nt < 4; nt++)
            #pragma unroll
            for (int j = 0; j < 4; j++) acc[mt][nt][j] = 0.f;

    issue(0, 0);
    issue(1, 1);

    for (int i = 0; i < 16; i++) {
        if (i + 1 < 16) cpwait<1>(); else cpwait<0>();
        __syncthreads();
        if (i + 2 < 16) issue(i + 2, (i + 2) % 3);

        const unsigned so = (unsigned)((i % 3) * QKV_STG * 2);
        #pragma unroll
        for (int ks = 0; ks < 4; ks++) {
            unsigned a[4][4];
            #pragma unroll
            for (int mt = 0; mt < 4; mt++)
                ldsm4(a[mt], aBase + so + mt * (16 * QKST * 2) + ks * 32);
            #pragma unroll
            for (int p = 0; p < 2; p++) {
                unsigned bb[4];
                ldsm4(bb, bBase + so + p * (16 * QKST * 2) + ks * 32);
                #pragma unroll
                for (int mt = 0; mt < 4; mt++) {
                    mma16(acc[mt][2*p    ], a[mt], bb);
                    mma16(acc[mt][2*p + 1], a[mt], bb + 2);
                }
            }
        }
    }

    // epilogue: bias, scale (Q only), pack bf16, scatter to [B,H,S,D]
    #pragma unroll
    for (int nt = 0; nt < 4; nt++) {
        int coln = n0 + wn * 32 + nt * 8 + 2 * t;
        int h = coln >> 6, d = coln & 63;
        float bv0 = bias[coln], bv1 = bias[coln + 1];
        #pragma unroll
        for (int mt = 0; mt < 4; mt++) {
            int gm = m0 + wm * 64 + mt * 16 + g;
            int bb = gm >> 11, s = gm & (S_ - 1);
            __nv_bfloat16* op = out + (size_t)((bb*H_ + h)*S_ + s) * D_ + d;
            *(unsigned*)op = pack_bf2((acc[mt][nt][0] + bv0) * qsc,
                                      (acc[mt][nt][1] + bv1) * qsc);
            *(unsigned*)(op + 8*D_) = pack_bf2((acc[mt][nt][2] + bv0) * qsc,
                                               (acc[mt][nt][3] + bv1) * qsc);
        }
    }
}

// =====================================================================
// Flash attention: bf16 mma + ldmatrix + ex2 softmax (log2 domain).
// 128 q rows/block (8 warps x 16), key tile 64. Double-buffered K/V,
// Q fragments hoisted to registers, P stays in registers.
// =====================================================================
#define AST 72
#define Q_BYTES   (128 * AST * 2)
#define KV_BYTES  (64 * AST * 2)
#define ATTN_SMEM (Q_BYTES + 4 * KV_BYTES + 2 * 64 * 4 + 64 * 4)

__global__ __launch_bounds__(256, 2) void attn_mma(const int* __restrict__ mask)
{
    extern __shared__ __align__(16) char smraw[];
    __nv_bfloat16* Qs = (__nv_bfloat16*)smraw;          // [128][AST]
    __nv_bfloat16* Ks = Qs + 128 * AST;                 // buf0: K,V ; buf1: K,V
    __nv_bfloat16* Vs = Ks + 64 * AST;
    float* smf   = (float*)(smraw + Q_BYTES + 4 * KV_BYTES);  // [2][64]
    float* spool = smf + 128;                                 // [64]

    const int tid  = threadIdx.x;
    const int lane = tid & 31, wid = tid >> 5;
    const int g = lane >> 2, t = lane & 3;
    const int wrow = wid * 16;
    const int bh = blockIdx.y, b = bh >> 4;
    const int m0 = blockIdx.x * 128;
    const unsigned KVB = 2 * KV_BYTES;

    const __nv_bfloat16* Qg = g_Qb + (size_t)(bh * S_ + m0) * D_;
    const __nv_bfloat16* Kg = g_Kb + (size_t)bh * S_ * D_;
    const __nv_bfloat16* Vg = g_Vb + (size_t)bh * S_ * D_;

    const unsigned qA = sptr(&Qs[(wrow + (lane & 15)) * AST + (lane >> 4) * 8]);
    const unsigned kB = sptr(&Ks[((lane & 7) + ((lane & 16) >> 1)) * AST + ((lane >> 3) & 1) * 8]);
    const unsigned vB = sptr(&Vs[(lane & 15) * AST + (lane >> 4) * 8]);

    // Q tile: straight bf16 copy (already pre-scaled)
    #pragma unroll
    for (int it = 0; it < 4; it++) {
        int lin = tid + it * 256;
        int rr = lin >> 3, c8 = (lin & 7) * 8;
        *(uint4*)&Qs[rr * AST + c8] = *(const uint4*)(Qg + (size_t)rr * D_ + c8);
    }
    if (tid < 64) spool[tid] = 0.f;

    float oac[8][4];
    #pragma unroll
    for (int dt = 0; dt < 8; dt++)
        #pragma unroll
        for (int j = 0; j < 4; j++) oac[dt][j] = 0.f;
    float lsum0 = 0.f, lsum1 = 0.f;

    const int rr0 = tid >> 3, c8_ = (tid & 7) * 8;
    const int rr1 = rr0 + 32;

    // prologue: tile0 -> buf0, stage tile1 in regs
    uint4 pk[2], pv[2]; int pm = 1;
    pk[0] = *(const uint4*)(Kg + (size_t)rr0 * D_ + c8_);
    pk[1] = *(const uint4*)(Kg + (size_t)rr1 * D_ + c8_);
    pv[0] = *(const uint4*)(Vg + (size_t)rr0 * D_ + c8_);
    pv[1] = *(const uint4*)(Vg + (size_t)rr1 * D_ + c8_);
    *(uint4*)&Ks[rr0 * AST + c8_] = pk[0];
    *(uint4*)&Ks[rr1 * AST + c8_] = pk[1];
    *(uint4*)&Vs[rr0 * AST + c8_] = pv[0];
    *(uint4*)&Vs[rr1 * AST + c8_] = pv[1];
    if (tid < 64) smf[tid] = mask[b * S_ + tid] ? 0.f : -1e9f;
    pk[0] = *(const uint4*)(Kg + (size_t)(64 + rr0) * D_ + c8_);
    pk[1] = *(const uint4*)(Kg + (size_t)(64 + rr1) * D_ + c8_);
    pv[0] = *(const uint4*)(Vg + (size_t)(64 + rr0) * D_ + c8_);
    pv[1] = *(const uint4*)(Vg + (size_t)(64 + rr1) * D_ + c8_);
    if (tid < 64) pm = mask[b * S_ + 64 + tid];
    __syncthreads();

    // hoist Q fragments (loop-invariant across key tiles)
    unsigned qa[4][4];
    #pragma unroll
    for (int ks = 0; ks < 4; ks++) ldsm4(qa[ks], qA + ks * 32);

    for (int i = 0; i < 32; i++) {
        const unsigned cb = (i & 1) * KVB;
        const int nxt = (i + 1) & 1;
        if (i + 1 < 32) {
            __nv_bfloat16* Kn = Ks + nxt * (KVB / 2);
            __nv_bfloat16* Vn = Vs + nxt * (KVB / 2);
            *(uint4*)&Kn[rr0 * AST + c8_] = pk[0];
            *(uint4*)&Kn[rr1 * AST + c8_] = pk[1];
            *(uint4*)&Vn[rr0 * AST + c8_] = pv[0];
            *(uint4*)&Vn[rr1 * AST + c8_] = pv[1];
            if (tid < 64) smf[nxt * 64 + tid] = pm ? 0.f : -1e9f;
        }
        if (i + 2 < 32) {
            size_t base = (size_t)((i + 2) * 64);
            pk[0] = *(const uint4*)(Kg + (base + rr0) * D_ + c8_);
            pk[1] = *(const uint4*)(Kg + (base + rr1) * D_ + c8_);
            pv[0] = *(const uint4*)(Vg + (base + rr0) * D_ + c8_);
            pv[1] = *(const uint4*)(Vg + (base + rr1) * D_ + c8_);
            if (tid < 64) pm = mask[b * S_ + (i + 2) * 64 + tid];
        }

        // ---- S = Q K^T (log2 domain) ----
        float sc[8][4];
        #pragma unroll
        for (int nt = 0; nt < 8; nt++)
            #pragma unroll
            for (int j = 0; j < 4; j++) sc[nt][j] = 0.f;

        #pragma unroll
        for (int ks = 0; ks < 4; ks++) {
            #pragma unroll
            for (int p = 0; p < 4; p++) {
                unsigned bb[4];
                ldsm4(bb, kB + cb + p * (16 * AST * 2) + ks * 32);
                mma16(sc[2*p    ], qa[ks], bb);
                mma16(sc[2*p + 1], qa[ks], bb + 2);
            }
        }

        // ---- exp via MUFU ex2, lsum, pack directly into PV A-fragments ----
        unsigned pfrag[16];
        const float* mfb = smf + (i & 1) * 64;
        #pragma unroll
        for (int nt = 0; nt < 8; nt++) {
            float2 mf = *(const float2*)&mfb[nt*8 + 2*t];
            float e0 = ex2f(sc[nt][0] + mf.x);
            float e1 = ex2f(sc[nt][1] + mf.y);
            float e2 = ex2f(sc[nt][2] + mf.x);
            float e3 = ex2f(sc[nt][3] + mf.y);
            lsum0 += e0 + e1;
            lsum1 += e2 + e3;
            pfrag[2*nt    ] = pack_bf2(e0, e1);
            pfrag[2*nt + 1] = pack_bf2(e2, e3);
        }

        // ---- O += P V ----
        #pragma unroll
        for (int ks = 0; ks < 4; ks++) {
            #pragma unroll
            for (int p = 0; p < 4; p++) {
                unsigned bb[4];
                ldsm4t(bb, vB + cb + ks * (16 * AST * 2) + p * 32);
                mma16(oac[2*p    ], &pfrag[4*ks], bb);
                mma16(oac[2*p + 1], &pfrag[4*ks], bb + 2);
            }
        }
        __syncthreads();
    }

    // ---- epilogue: normalize rows, block-local pooled reduction ----
    lsum0 += __shfl_xor_sync(0xffffffffu, lsum0, 1);
    lsum0 += __shfl_xor_sync(0xffffffffu, lsum0, 2);
    lsum1 += __shfl_xor_sync(0xffffffffu, lsum1, 1);
    lsum1 += __shfl_xor_sync(0xffffffffu, lsum1, 2);
    float inv0 = 1.f / lsum0, inv1 = 1.f / lsum1;

    #pragma unroll
    for (int dt = 0; dt < 8; dt++) {
        float p0 = oac[dt][0] * inv0 + oac[dt][2] * inv1;
        float p1 = oac[dt][1] * inv0 + oac[dt][3] * inv1;
        p0 += __shfl_xor_sync(0xffffffffu, p0, 4);
        p0 += __shfl_xor_sync(0xffffffffu, p0, 8);
        p0 += __shfl_xor_sync(0xffffffffu, p0, 16);
        p1 += __shfl_xor_sync(0xffffffffu, p1, 4);
        p1 += __shfl_xor_sync(0xffffffffu, p1, 8);
        p1 += __shfl_xor_sync(0xffffffffu, p1, 16);
        if (lane < 4) {
            atomicAdd(&spool[dt*8 + 2*t    ], p0);
            atomicAdd(&spool[dt*8 + 2*t + 1], p1);
        }
    }
    __syncthreads();
    if (tid < 64) {
        const int h = bh & 15;
        atomicAdd(&g_pooled[b*E_ + h*64 + tid], spool[tid]);
    }
}

// =====================================================================
// head A: o = (pooled/S) @ Wo^T + bo ; accumulate squared norm
// =====================================================================
__global__ __launch_bounds__(256) void headA_kernel(
    const float* __restrict__ Wo, const float* __restrict__ bo)
{
    const int b = blockIdx.y;
    const int n = blockIdx.x * 8 + (threadIdx.x >> 5);
    const int lane = threadIdx.x & 31;
    const float* pr = g_pooled + b * E_;
    const float* wr = Wo + (size_t)n * E_;
    float acc = 0.f;
    #pragma unroll
    for (int i = 0; i < 8; i++) {
        int k = i * 128 + lane * 4;
        float4 w = *(const float4*)(wr + k);
        float4 p = *(const float4*)(pr + k);
        acc += p.x*w.x + p.y*w.y + p.z*w.z + p.w*w.w;
    }
    #pragma unroll
    for (int off = 16; off > 0; off >>= 1)
        acc += __shfl_xor_sync(0xffffffffu, acc, off);
    if (lane == 0) {
        float o = acc * (1.0f / S_) + bo[n];
        g_o[b * E_ + n] = o;
        atomicAdd(&g_nrm[b], o * o);
    }
}

// =====================================================================
// head B: u = o/||o|| - text ; h = relu(u @ W1^T + b1) ; score += h*W2
// =====================================================================
__global__ __launch_bounds__(256) void headB_kernel(
    const float* __restrict__ text,
    const float* __restrict__ W1, const float* __restrict__ b1,
    const float* __restrict__ W2)
{
    const int b = blockIdx.y;
    const int rr = blockIdx.x * 8 + (threadIdx.x >> 5);
    const int lane = threadIdx.x & 31;
    const float rinv = rsqrtf(g_nrm[b]);
    const float* orow = g_o + b * E_;
    const float* trow = text + b * E_;
    const float* wr = W1 + (size_t)rr * E_;
    float acc = 0.f;
    #pragma unroll
    for (int i = 0; i < 8; i++) {
        int k = i * 128 + lane * 4;
        float4 w = *(const float4*)(wr + k);
        float4 o = *(const float4*)(orow + k);
        float4 tt = *(const float4*)(trow + k);
        acc += (o.x*rinv - tt.x)*w.x + (o.y*rinv - tt.y)*w.y
             + (o.z*rinv - tt.z)*w.z + (o.w*rinv - tt.w)*w.w;
    }
    #pragma unroll
    for (int off = 16; off > 0; off >>= 1)
        acc += __shfl_xor_sync(0xffffffffu, acc, off);
    if (lane == 0) {
        float hv = fmaxf(acc + b1[rr], 0.f);
        atomicAdd(&g_score[b], hv * W2[rr]);
    }
}

__global__ void headC_kernel(const float* __restrict__ b2, float* __restrict__ out)
{
    int i = threadIdx.x;
    if (i < B_) out[i] = tanhf(g_score[i] + b2[0]);
}

// =====================================================================
// Launch
// =====================================================================
extern "C" void kernel_launch(void* const* d_in, const int* in_sizes, int n_in,
                              void* d_out, int out_size)
{
    (void)in_sizes; (void)n_in; (void)out_size;
    const float* x    = (const float*)d_in[0];
    const int*   mask = (const int*)  d_in[1];
    const float* text = (const float*)d_in[2];
    const float* Wq = (const float*)d_in[3];
    const float* bq = (const float*)d_in[4];
    const float* Wk = (const float*)d_in[5];
    const float* bk = (const float*)d_in[6];
    const float* Wv = (const float*)d_in[7];
    const float* bv = (const float*)d_in[8];
    const float* Wo = (const float*)d_in[9];
    const float* bo = (const float*)d_in[10];
    const float* W1 = (const float*)d_in[11];
    const float* b1 = (const float*)d_in[12];
    const float* W2 = (const float*)d_in[13];
    const float* b2 = (const float*)d_in[14];
    float* out = (float*)d_out;

    cudaFuncSetAttribute(attn_mma, cudaFuncAttributeMaxDynamicSharedMemorySize, ATTN_SMEM);
    cudaFuncSetAttribute(qkv_mma, cudaFuncAttributeMaxDynamicSharedMemorySize, QKV_SMEM);

    zero_kernel<<<16, 256>>>();
    {
        int total = (XN + 3*WN) / 4;
        cvt_kernel<<<(total + 255) / 256, 256>>>(x, Wq, Wk, Wv);
    }
    qkv_mma<<<dim3(8, 64, 3), 256, QKV_SMEM>>>(bq, bk, bv);
    attn_mma<<<dim3(16, 64), 256, ATTN_SMEM>>>(mask);
    headA_kernel<<<dim3(128, B_), 256>>>(Wo, bo);
    headB_kernel<<<dim3(64, B_), 256>>>(text, W1, b1, W2);
    headC_kernel<<<1, 32>>>(b2, out);
}

// round 12
// speedup vs baseline: 2.4890x; 1.0112x over previous
#include <cuda_runtime.h>
#include <cuda_bf16.h>

// Problem constants
#define B_ 4
#define S_ 2048
#define E_ 1024
#define H_ 16
#define D_ 64
#define XN (B_*S_*E_)     // 8388608
#define WN (E_*E_)        // 1048576

// ---------------- scratch ----------------
__device__ __nv_bfloat16 g_xb[XN];            // bf16 copy of x
__device__ __nv_bfloat16 g_Wb[3*WN];          // bf16 Wq|Wk|Wv
__device__ __nv_bfloat16 g_Qb[B_*H_*S_*D_];   // pre-scaled by 0.125*log2e
__device__ __nv_bfloat16 g_Kb[B_*H_*S_*D_];
__device__ __nv_bfloat16 g_Vb[B_*H_*S_*D_];
__device__ float g_pooled[B_*E_];
__device__ float g_o[B_*E_];
__device__ float g_nrm[B_];
__device__ float g_score[B_];

// ---------------- helpers ----------------
__device__ __forceinline__ void mma16(float* c, const unsigned* a, const unsigned* b) {
    asm("mma.sync.aligned.m16n8k16.row.col.f32.bf16.bf16.f32 "
        "{%0,%1,%2,%3}, {%4,%5,%6,%7}, {%8,%9}, {%0,%1,%2,%3};"
        : "+f"(c[0]), "+f"(c[1]), "+f"(c[2]), "+f"(c[3])
        : "r"(a[0]), "r"(a[1]), "r"(a[2]), "r"(a[3]), "r"(b[0]), "r"(b[1]));
}
__device__ __forceinline__ unsigned pack_bf2(float lo, float hi) {
    __nv_bfloat162 h = __floats2bfloat162_rn(lo, hi);
    return *reinterpret_cast<unsigned*>(&h);
}
__device__ __forceinline__ float ex2f(float x) {
    float r; asm("ex2.approx.f32 %0, %1;" : "=f"(r) : "f"(x)); return r;
}
__device__ __forceinline__ unsigned sptr(const void* p) {
    return (unsigned)__cvta_generic_to_shared(p);
}
__device__ __forceinline__ void ldsm4(unsigned* r, unsigned addr) {
    asm volatile("ldmatrix.sync.aligned.m8n8.x4.shared.b16 {%0,%1,%2,%3}, [%4];"
        : "=r"(r[0]), "=r"(r[1]), "=r"(r[2]), "=r"(r[3]) : "r"(addr));
}
__device__ __forceinline__ void ldsm4t(unsigned* r, unsigned addr) {
    asm volatile("ldmatrix.sync.aligned.m8n8.x4.trans.shared.b16 {%0,%1,%2,%3}, [%4];"
        : "=r"(r[0]), "=r"(r[1]), "=r"(r[2]), "=r"(r[3]) : "r"(addr));
}
__device__ __forceinline__ void cpa16(unsigned s, const void* g) {
    asm volatile("cp.async.cg.shared.global [%0], [%1], 16;" :: "r"(s), "l"(g));
}
__device__ __forceinline__ void cpcommit() { asm volatile("cp.async.commit_group;"); }
template<int N> __device__ __forceinline__ void cpwait() {
    asm volatile("cp.async.wait_group %0;" :: "n"(N));
}

#define QSCALE 0.18033688011112042f   // (1/sqrt(64)) * log2(e)

// =====================================================================
// zero scratch accumulators
// =====================================================================
__global__ void zero_kernel() {
    int i = blockIdx.x * blockDim.x + threadIdx.x;
    if (i < B_*E_) g_pooled[i] = 0.f;
    if (i < B_) { g_nrm[i] = 0.f; g_score[i] = 0.f; }
}

// =====================================================================
// one-shot fp32 -> bf16 conversion of x and Wq/Wk/Wv
// =====================================================================
__global__ __launch_bounds__(256) void cvt_kernel(
    const float* __restrict__ x,
    const float* __restrict__ Wq, const float* __restrict__ Wk,
    const float* __restrict__ Wv)
{
    const int i = blockIdx.x * blockDim.x + threadIdx.x;
    const int total = (XN + 3*WN) / 4;
    if (i >= total) return;
    int v = i * 4;
    const float* src;
    __nv_bfloat16* dst;
    if (v < XN) {
        src = x + v; dst = g_xb + v;
    } else {
        int w = v - XN;
        int z = w / WN, r = w - z * WN;
        src = (z == 0 ? Wq : (z == 1 ? Wk : Wv)) + r;
        dst = g_Wb + z * WN + r;
    }
    float4 f = *(const float4*)src;
    *(uint2*)dst = make_uint2(pack_bf2(f.x, f.y), pack_bf2(f.z, f.w));
}

// =====================================================================
// QKV projection via bf16 mma on bf16 inputs -> bf16 scatter [B,H,S,D]
// BM=BN=128 BK=64, 256 thr (8 warps 2x4), warp tile 64x32.
// cp.async 3-stage pipeline, one sync per k-iter (16 iters).
// =====================================================================
#define QKST 72
#define QKV_STG (128 * QKST)
#define QKV_SMEM (3 * 2 * QKV_STG * 2)

__global__ __launch_bounds__(256) void qkv_mma(
    const float* __restrict__ bq, const float* __restrict__ bk,
    const float* __restrict__ bv)
{
    extern __shared__ __align__(16) char qsm[];
    __nv_bfloat16* As = (__nv_bfloat16*)qsm;
    __nv_bfloat16* Bs = As + 3 * QKV_STG;

    const int z = blockIdx.z;
    const float* __restrict__ bias = (z == 0) ? bq : ((z == 1) ? bk : bv);
    __nv_bfloat16* __restrict__ out = (z == 0) ? g_Qb : ((z == 1) ? g_Kb : g_Vb);
    const float qsc = (z == 0) ? QSCALE : 1.f;

    const int tid  = threadIdx.x;
    const int lane = tid & 31, wid = tid >> 5;
    const int wm = wid >> 2, wn = wid & 3;
    const int m0 = blockIdx.y * 128, n0 = blockIdx.x * 128;
    const int g = lane >> 2, t = lane & 3;

    const __nv_bfloat16* Xg = g_xb + (size_t)m0 * E_;
    const __nv_bfloat16* Wg = g_Wb + (size_t)z * WN + (size_t)n0 * E_;

    const int crow = tid >> 3;
    const int ccol = (tid & 7) * 8;

    const unsigned aS0 = sptr(As) + (unsigned)(crow * QKST + ccol) * 2;
    const unsigned bS0 = sptr(Bs) + (unsigned)(crow * QKST + ccol) * 2;

    auto issue = [&](int kt, int s) {
        unsigned so = (unsigned)(s * QKV_STG * 2);
        const __nv_bfloat16* xa = Xg + (size_t)crow * E_ + kt * 64 + ccol;
        const __nv_bfloat16* wb = Wg + (size_t)crow * E_ + kt * 64 + ccol;
        #pragma unroll
        for (int it = 0; it < 4; it++) {
            cpa16(aS0 + so + it * (32 * QKST * 2), xa + (size_t)(it * 32) * E_);
            cpa16(bS0 + so + it * (32 * QKST * 2), wb + (size_t)(it * 32) * E_);
        }
        cpcommit();
    };

    const unsigned aBase = sptr(As) +
        (unsigned)((wm*64 + (lane & 15)) * QKST + (lane >> 4) * 8) * 2;
    const unsigned bBase = sptr(Bs) +
        (unsigned)((wn*32 + (lane & 7) + ((lane & 16) >> 1)) * QKST + ((lane >> 3) & 1) * 8) * 2;

    float acc[4][4][4];
    #pragma unroll
    for (int mt = 0; mt < 4; mt++)
        #pragma unroll
        for (int nt = 0; nt < 4; nt++)
            #pragma unroll
            for (int j = 0; j < 4; j++) acc[mt][nt][j] = 0.f;

    issue(0, 0);
    issue(1, 1);

    for (int i = 0; i < 16; i++) {
        if (i + 1 < 16) cpwait<1>(); else cpwait<0>();
        __syncthreads();
        if (i + 2 < 16) issue(i + 2, (i + 2) % 3);

        const unsigned so = (unsigned)((i % 3) * QKV_STG * 2);
        #pragma unroll
        for (int ks = 0; ks < 4; ks++) {
            unsigned a[4][4];
            #pragma unroll
            for (int mt = 0; mt < 4; mt++)
                ldsm4(a[mt], aBase + so + mt * (16 * QKST * 2) + ks * 32);
            #pragma unroll
            for (int p = 0; p < 2; p++) {
                unsigned bb[4];
                ldsm4(bb, bBase + so + p * (16 * QKST * 2) + ks * 32);
                #pragma unroll
                for (int mt = 0; mt < 4; mt++) {
                    mma16(acc[mt][2*p    ], a[mt], bb);
                    mma16(acc[mt][2*p + 1], a[mt], bb + 2);
                }
            }
        }
    }

    #pragma unroll
    for (int nt = 0; nt < 4; nt++) {
        int coln = n0 + wn * 32 + nt * 8 + 2 * t;
        int h = coln >> 6, d = coln & 63;
        float bv0 = bias[coln], bv1 = bias[coln + 1];
        #pragma unroll
        for (int mt = 0; mt < 4; mt++) {
            int gm = m0 + wm * 64 + mt * 16 + g;
            int bb = gm >> 11, s = gm & (S_ - 1);
            __nv_bfloat16* op = out + (size_t)((bb*H_ + h)*S_ + s) * D_ + d;
            *(unsigned*)op = pack_bf2((acc[mt][nt][0] + bv0) * qsc,
                                      (acc[mt][nt][1] + bv1) * qsc);
            *(unsigned*)(op + 8*D_) = pack_bf2((acc[mt][nt][2] + bv0) * qsc,
                                               (acc[mt][nt][3] + bv1) * qsc);
        }
    }
}

// =====================================================================
// Flash attention: bf16 mma + ldmatrix + ex2 softmax (log2 domain).
// 256 q rows/block: 8 warps x 32 rows (mt=2) -> B-fragments amortized
// over 2x MMAs (128B smem/MMA, was 256B). Key tile 64, double-buffered
// K/V, Q and P fragments in registers, QK split in two nt-halves.
// =====================================================================
#define AST 72
#define QROWS 256
#define Q_BYTES   (QROWS * AST * 2)
#define KV_BYTES  (64 * AST * 2)
#define ATTN_SMEM (Q_BYTES + 4 * KV_BYTES + 2 * 64 * 4 + 64 * 4)

__global__ __launch_bounds__(256, 1) void attn_mma(const int* __restrict__ mask)
{
    extern __shared__ __align__(16) char smraw[];
    __nv_bfloat16* Qs = (__nv_bfloat16*)smraw;          // [256][AST]
    __nv_bfloat16* Ks = Qs + QROWS * AST;               // buf0: K,V ; buf1: K,V
    __nv_bfloat16* Vs = Ks + 64 * AST;
    float* smf   = (float*)(smraw + Q_BYTES + 4 * KV_BYTES);  // [2][64]
    float* spool = smf + 128;                                 // [64]

    const int tid  = threadIdx.x;
    const int lane = tid & 31, wid = tid >> 5;
    const int t = lane & 3;
    const int wrow = wid * 32;
    const int bh = blockIdx.y, b = bh >> 4;
    const int m0 = blockIdx.x * QROWS;
    const unsigned KVB = 2 * KV_BYTES;

    const __nv_bfloat16* Qg = g_Qb + (size_t)(bh * S_ + m0) * D_;
    const __nv_bfloat16* Kg = g_Kb + (size_t)bh * S_ * D_;
    const __nv_bfloat16* Vg = g_Vb + (size_t)bh * S_ * D_;

    const unsigned qA = sptr(&Qs[(wrow + (lane & 15)) * AST + (lane >> 4) * 8]);
    const unsigned kB = sptr(&Ks[((lane & 7) + ((lane & 16) >> 1)) * AST + ((lane >> 3) & 1) * 8]);
    const unsigned vB = sptr(&Vs[(lane & 15) * AST + (lane >> 4) * 8]);

    // Q tile: straight bf16 copy (already pre-scaled)
    #pragma unroll
    for (int it = 0; it < 8; it++) {
        int lin = tid + it * 256;                 // 0..2047
        int rr = lin >> 3, c8 = (lin & 7) * 8;
        *(uint4*)&Qs[rr * AST + c8] = *(const uint4*)(Qg + (size_t)rr * D_ + c8);
    }
    if (tid < 64) spool[tid] = 0.f;

    float oac[2][8][4];
    #pragma unroll
    for (int mt = 0; mt < 2; mt++)
        #pragma unroll
        for (int dt = 0; dt < 8; dt++)
            #pragma unroll
            for (int j = 0; j < 4; j++) oac[mt][dt][j] = 0.f;
    float lsum[2][2] = {{0.f, 0.f}, {0.f, 0.f}};

    const int rr0 = tid >> 3, c8_ = (tid & 7) * 8;
    const int rr1 = rr0 + 32;

    // prologue: tile0 -> buf0, stage tile1 in regs
    uint4 pk[2], pv[2]; int pm = 1;
    pk[0] = *(const uint4*)(Kg + (size_t)rr0 * D_ + c8_);
    pk[1] = *(const uint4*)(Kg + (size_t)rr1 * D_ + c8_);
    pv[0] = *(const uint4*)(Vg + (size_t)rr0 * D_ + c8_);
    pv[1] = *(const uint4*)(Vg + (size_t)rr1 * D_ + c8_);
    *(uint4*)&Ks[rr0 * AST + c8_] = pk[0];
    *(uint4*)&Ks[rr1 * AST + c8_] = pk[1];
    *(uint4*)&Vs[rr0 * AST + c8_] = pv[0];
    *(uint4*)&Vs[rr1 * AST + c8_] = pv[1];
    if (tid < 64) smf[tid] = mask[b * S_ + tid] ? 0.f : -1e9f;
    pk[0] = *(const uint4*)(Kg + (size_t)(64 + rr0) * D_ + c8_);
    pk[1] = *(const uint4*)(Kg + (size_t)(64 + rr1) * D_ + c8_);
    pv[0] = *(const uint4*)(Vg + (size_t)(64 + rr0) * D_ + c8_);
    pv[1] = *(const uint4*)(Vg + (size_t)(64 + rr1) * D_ + c8_);
    if (tid < 64) pm = mask[b * S_ + 64 + tid];
    __syncthreads();

    // hoist Q fragments: qa[ks][mt][4]
    unsigned qa[4][2][4];
    #pragma unroll
    for (int ks = 0; ks < 4; ks++)
        #pragma unroll
        for (int mt = 0; mt < 2; mt++)
            ldsm4(qa[ks][mt], qA + mt * (16 * AST * 2) + ks * 32);

    for (int i = 0; i < 32; i++) {
        const unsigned cb = (i & 1) * KVB;
        const int nxt = (i + 1) & 1;
        if (i + 1 < 32) {
            __nv_bfloat16* Kn = Ks + nxt * (KVB / 2);
            __nv_bfloat16* Vn = Vs + nxt * (KVB / 2);
            *(uint4*)&Kn[rr0 * AST + c8_] = pk[0];
            *(uint4*)&Kn[rr1 * AST + c8_] = pk[1];
            *(uint4*)&Vn[rr0 * AST + c8_] = pv[0];
            *(uint4*)&Vn[rr1 * AST + c8_] = pv[1];
            if (tid < 64) smf[nxt * 64 + tid] = pm ? 0.f : -1e9f;
        }
        if (i + 2 < 32) {
            size_t base = (size_t)((i + 2) * 64);
            pk[0] = *(const uint4*)(Kg + (base + rr0) * D_ + c8_);
            pk[1] = *(const uint4*)(Kg + (base + rr1) * D_ + c8_);
            pv[0] = *(const uint4*)(Vg + (base + rr0) * D_ + c8_);
            pv[1] = *(const uint4*)(Vg + (base + rr1) * D_ + c8_);
            if (tid < 64) pm = mask[b * S_ + (i + 2) * 64 + tid];
        }

        // ---- QK + exp in two nt-halves (keeps sc live set small) ----
        unsigned pfrag[2][16];
        const float* mfb = smf + (i & 1) * 64;
        #pragma unroll
        for (int h = 0; h < 2; h++) {
            float sc[2][4][4];
            #pragma unroll
            for (int mt = 0; mt < 2; mt++)
                #pragma unroll
                for (int l = 0; l < 4; l++)
                    #pragma unroll
                    for (int j = 0; j < 4; j++) sc[mt][l][j] = 0.f;

            #pragma unroll
            for (int ks = 0; ks < 4; ks++) {
                #pragma unroll
                for (int pp = 0; pp < 2; pp++) {
                    int p = 2*h + pp;
                    unsigned bb[4];
                    ldsm4(bb, kB + cb + p * (16 * AST * 2) + ks * 32);
                    #pragma unroll
                    for (int mt = 0; mt < 2; mt++) {
                        mma16(sc[mt][2*pp    ], qa[ks][mt], bb);
                        mma16(sc[mt][2*pp + 1], qa[ks][mt], bb + 2);
                    }
                }
            }
            #pragma unroll
            for (int l = 0; l < 4; l++) {
                int gnt = 4*h + l;
                float2 mf = *(const float2*)&mfb[gnt*8 + 2*t];
                #pragma unroll
                for (int mt = 0; mt < 2; mt++) {
                    float e0 = ex2f(sc[mt][l][0] + mf.x);
                    float e1 = ex2f(sc[mt][l][1] + mf.y);
                    float e2 = ex2f(sc[mt][l][2] + mf.x);
                    float e3 = ex2f(sc[mt][l][3] + mf.y);
                    lsum[mt][0] += e0 + e1;
                    lsum[mt][1] += e2 + e3;
                    pfrag[mt][2*gnt    ] = pack_bf2(e0, e1);
                    pfrag[mt][2*gnt + 1] = pack_bf2(e2, e3);
                }
            }
        }

        // ---- O += P V ----
        #pragma unroll
        for (int ks = 0; ks < 4; ks++) {
            #pragma unroll
            for (int p = 0; p < 4; p++) {
                unsigned bb[4];
                ldsm4t(bb, vB + cb + ks * (16 * AST * 2) + p * 32);
                #pragma unroll
                for (int mt = 0; mt < 2; mt++) {
                    mma16(oac[mt][2*p    ], &pfrag[mt][4*ks], bb);
                    mma16(oac[mt][2*p + 1], &pfrag[mt][4*ks], bb + 2);
                }
            }
        }
        __syncthreads();
    }

    // ---- epilogue: normalize rows, block-local pooled reduction ----
    #pragma unroll
    for (int mt = 0; mt < 2; mt++)
        #pragma unroll
        for (int j = 0; j < 2; j++) {
            float v = lsum[mt][j];
            v += __shfl_xor_sync(0xffffffffu, v, 1);
            v += __shfl_xor_sync(0xffffffffu, v, 2);
            lsum[mt][j] = 1.f / v;
        }

    #pragma unroll
    for (int dt = 0; dt < 8; dt++) {
        float p0 = oac[0][dt][0]*lsum[0][0] + oac[0][dt][2]*lsum[0][1]
                 + oac[1][dt][0]*lsum[1][0] + oac[1][dt][2]*lsum[1][1];
        float p1 = oac[0][dt][1]*lsum[0][0] + oac[0][dt][3]*lsum[0][1]
                 + oac[1][dt][1]*lsum[1][0] + oac[1][dt][3]*lsum[1][1];
        p0 += __shfl_xor_sync(0xffffffffu, p0, 4);
        p0 += __shfl_xor_sync(0xffffffffu, p0, 8);
        p0 += __shfl_xor_sync(0xffffffffu, p0, 16);
        p1 += __shfl_xor_sync(0xffffffffu, p1, 4);
        p1 += __shfl_xor_sync(0xffffffffu, p1, 8);
        p1 += __shfl_xor_sync(0xffffffffu, p1, 16);
        if (lane < 4) {
            atomicAdd(&spool[dt*8 + 2*t    ], p0);
            atomicAdd(&spool[dt*8 + 2*t + 1], p1);
        }
    }
    __syncthreads();
    if (tid < 64) {
        const int h = bh & 15;
        atomicAdd(&g_pooled[b*E_ + h*64 + tid], spool[tid]);
    }
}

// =====================================================================
// head A: o = (pooled/S) @ Wo^T + bo ; accumulate squared norm
// =====================================================================
__global__ __launch_bounds__(256) void headA_kernel(
    const float* __restrict__ Wo, const float* __restrict__ bo)
{
    const int b = blockIdx.y;
    const int n = blockIdx.x * 8 + (threadIdx.x >> 5);
    const int lane = threadIdx.x & 31;
    const float* pr = g_pooled + b * E_;
    const float* wr = Wo + (size_t)n * E_;
    float acc = 0.f;
    #pragma unroll
    for (int i = 0; i < 8; i++) {
        int k = i * 128 + lane * 4;
        float4 w = *(const float4*)(wr + k);
        float4 p = *(const float4*)(pr + k);
        acc += p.x*w.x + p.y*w.y + p.z*w.z + p.w*w.w;
    }
    #pragma unroll
    for (int off = 16; off > 0; off >>= 1)
        acc += __shfl_xor_sync(0xffffffffu, acc, off);
    if (lane == 0) {
        float o = acc * (1.0f / S_) + bo[n];
        g_o[b * E_ + n] = o;
        atomicAdd(&g_nrm[b], o * o);
    }
}

// =====================================================================
// head B: u = o/||o|| - text ; h = relu(u @ W1^T + b1) ; score += h*W2
// =====================================================================
__global__ __launch_bounds__(256) void headB_kernel(
    const float* __restrict__ text,
    const float* __restrict__ W1, const float* __restrict__ b1,
    const float* __restrict__ W2)
{
    const int b = blockIdx.y;
    const int rr = blockIdx.x * 8 + (threadIdx.x >> 5);
    const int lane = threadIdx.x & 31;
    const float rinv = rsqrtf(g_nrm[b]);
    const float* orow = g_o + b * E_;
    const float* trow = text + b * E_;
    const float* wr = W1 + (size_t)rr * E_;
    float acc = 0.f;
    #pragma unroll
    for (int i = 0; i < 8; i++) {
        int k = i * 128 + lane * 4;
        float4 w = *(const float4*)(wr + k);
        float4 o = *(const float4*)(orow + k);
        float4 tt = *(const float4*)(trow + k);
        acc += (o.x*rinv - tt.x)*w.x + (o.y*rinv - tt.y)*w.y
             + (o.z*rinv - tt.z)*w.z + (o.w*rinv - tt.w)*w.w;
    }
    #pragma unroll
    for (int off = 16; off > 0; off >>= 1)
        acc += __shfl_xor_sync(0xffffffffu, acc, off);
    if (lane == 0) {
        float hv = fmaxf(acc + b1[rr], 0.f);
        atomicAdd(&g_score[b], hv * W2[rr]);
    }
}

__global__ void headC_kernel(const float* __restrict__ b2, float* __restrict__ out)
{
    int i = threadIdx.x;
    if (i < B_) out[i] = tanhf(g_score[i] + b2[0]);
}

// =====================================================================
// Launch
// =====================================================================
extern "C" void kernel_launch(void* const* d_in, const int* in_sizes, int n_in,
                              void* d_out, int out_size)
{
    (void)in_sizes; (void)n_in; (void)out_size;
    const float* x    = (const float*)d_in[0];
    const int*   mask = (const int*)  d_in[1];
    const float* text = (const float*)d_in[2];
    const float* Wq = (const float*)d_in[3];
    const float* bq = (const float*)d_in[4];
    const float* Wk = (const float*)d_in[5];
    const float* bk = (const float*)d_in[6];
    const float* Wv = (const float*)d_in[7];
    const float* bv = (const float*)d_in[8];
    const float* Wo = (const float*)d_in[9];
    const float* bo = (const float*)d_in[10];
    const float* W1 = (const float*)d_in[11];
    const float* b1 = (const float*)d_in[12];
    const float* W2 = (const float*)d_in[13];
    const float* b2 = (const float*)d_in[14];
    float* out = (float*)d_out;

    cudaFuncSetAttribute(attn_mma, cudaFuncAttributeMaxDynamicSharedMemorySize, ATTN_SMEM);
    cudaFuncSetAttribute(qkv_mma, cudaFuncAttributeMaxDynamicSharedMemorySize, QKV_SMEM);

    zero_kernel<<<16, 256>>>();
    {
        int total = (XN + 3*WN) / 4;
        cvt_kernel<<<(total + 255) / 256, 256>>>(x, Wq, Wk, Wv);
    }
    qkv_mma<<<dim3(8, 64, 3), 256, QKV_SMEM>>>(bq, bk, bv);
    attn_mma<<<dim3(8, 64), 256, ATTN_SMEM>>>(mask);
    headA_kernel<<<dim3(128, B_), 256>>>(Wo, bo);
    headB_kernel<<<dim3(64, B_), 256>>>(text, W1, b1, W2);
    headC_kernel<<<1, 32>>>(b2, out);
}